// round 1
// baseline (speedup 1.0000x reference)
#include <cuda_runtime.h>
#include <cuda_bf16.h>
#include <math.h>

// Problem constants
#define BB 64
#define SS 512
#define DD 1024
#define HH 1024
#define G4H 4096          // 4*H
#define KW 2048           // D+H
#define OUT_MAIN 33554432 // B*S*H

// ---------------- device scratch (no allocs allowed) ----------------
__device__ float g_gx[(size_t)SS * BB * G4H];   // [s][b][4H]  512 MB
__device__ float g_wT[(size_t)KW * G4H];        // W^T: [D+H][4H]  32 MB
__device__ float g_h[2][BB * HH];
__device__ float g_c[BB * HH];

// ---------------- init: zero h0, c0 ----------------
__global__ void init_kernel() {
    int i = blockIdx.x * blockDim.x + threadIdx.x;
    if (i < BB * HH) {
        g_h[0][i] = 0.f;
        g_c[i] = 0.f;
    }
}

// ---------------- W transpose: W[4096][2048] -> g_wT[2048][4096] ----------------
__global__ __launch_bounds__(256) void transpose_kernel(const float* __restrict__ W) {
    __shared__ float tile[32][33];
    int c0 = blockIdx.x * 32;  // col of W (0..2047)
    int r0 = blockIdx.y * 32;  // row of W (0..4095)
    int tx = threadIdx.x, ty = threadIdx.y;  // 32 x 8
#pragma unroll
    for (int i = 0; i < 32; i += 8)
        tile[ty + i][tx] = W[(size_t)(r0 + ty + i) * KW + c0 + tx];
    __syncthreads();
#pragma unroll
    for (int i = 0; i < 32; i += 8)
        g_wT[(size_t)(c0 + ty + i) * G4H + r0 + tx] = tile[tx][ty + i];
}

// ---------------- big GEMM: Gx = X[32768x1024] @ wT[0:1024][4096] + bias ----------------
// 128x128 block tile, BK=8, 256 threads, 8x8 per thread, double-buffered smem.
__global__ __launch_bounds__(256) void gemm_x_kernel(const float* __restrict__ X,
                                                     const float* __restrict__ bias) {
    __shared__ float As[2][8][128];
    __shared__ float Bs[2][8][128];
    int tid = threadIdx.x;
    int bn = blockIdx.x;  // 0..31
    int bm = blockIdx.y;  // 0..255
    const float* Ab = X + (size_t)bm * 128 * DD;

    int arow = tid >> 1, ak = (tid & 1) * 4;       // A stage: one float4 each
    int bk = tid >> 5, bcol = (tid & 31) * 4;      // B stage: one float4 each

    float acc[8][8];
#pragma unroll
    for (int i = 0; i < 8; i++)
#pragma unroll
        for (int j = 0; j < 8; j++) acc[i][j] = 0.f;

    float4 av = *(const float4*)(Ab + (size_t)arow * DD + ak);
    float4 bv = *(const float4*)(g_wT + (size_t)bk * G4H + bn * 128 + bcol);
    As[0][ak + 0][arow] = av.x; As[0][ak + 1][arow] = av.y;
    As[0][ak + 2][arow] = av.z; As[0][ak + 3][arow] = av.w;
    *(float4*)&Bs[0][bk][bcol] = bv;
    __syncthreads();

    int buf = 0;
    int tx = tid & 15, ty = tid >> 4;

    for (int k0 = 0; k0 < DD; k0 += 8) {
        bool more = (k0 + 8) < DD;
        if (more) {
            av = *(const float4*)(Ab + (size_t)arow * DD + k0 + 8 + ak);
            bv = *(const float4*)(g_wT + (size_t)(k0 + 8 + bk) * G4H + bn * 128 + bcol);
        }
#pragma unroll
        for (int k = 0; k < 8; k++) {
            float a[8], b[8];
            *(float4*)&a[0] = *(const float4*)&As[buf][k][ty * 8];
            *(float4*)&a[4] = *(const float4*)&As[buf][k][ty * 8 + 4];
            *(float4*)&b[0] = *(const float4*)&Bs[buf][k][tx * 8];
            *(float4*)&b[4] = *(const float4*)&Bs[buf][k][tx * 8 + 4];
#pragma unroll
            for (int i = 0; i < 8; i++)
#pragma unroll
                for (int j = 0; j < 8; j++) acc[i][j] += a[i] * b[j];
        }
        if (more) {
            buf ^= 1;
            As[buf][ak + 0][arow] = av.x; As[buf][ak + 1][arow] = av.y;
            As[buf][ak + 2][arow] = av.z; As[buf][ak + 3][arow] = av.w;
            *(float4*)&Bs[buf][bk][bcol] = bv;
        }
        __syncthreads();
    }

    // epilogue: add bias, scatter to g_gx[s][b][n]   (A row r = b*512 + s)
    int ncol = bn * 128 + tx * 8;
    float4 bi0 = *(const float4*)(bias + ncol);
    float4 bi1 = *(const float4*)(bias + ncol + 4);
#pragma unroll
    for (int i = 0; i < 8; i++) {
        int r = bm * 128 + ty * 8 + i;
        int s = r & 511, b_ = r >> 9;
        size_t off = (size_t)(s * BB + b_) * G4H + ncol;
        float4 v0, v1;
        v0.x = acc[i][0] + bi0.x; v0.y = acc[i][1] + bi0.y;
        v0.z = acc[i][2] + bi0.z; v0.w = acc[i][3] + bi0.w;
        v1.x = acc[i][4] + bi1.x; v1.y = acc[i][5] + bi1.y;
        v1.z = acc[i][6] + bi1.z; v1.w = acc[i][7] + bi1.w;
        *(float4*)(g_gx + off) = v0;
        *(float4*)(g_gx + off + 4) = v1;
    }
}

// ---------------- recurrent step ----------------
// 128 blocks; block owns 8 H-columns -> 32 gate cols (i/f/o/g groups of 8).
// gates[64x32] = Gx_t + h_in[64x1024] @ whT[1024 x 32sel]; then cell update.
__global__ __launch_bounds__(256) void lstm_step_kernel(float* __restrict__ outp, int t) {
    __shared__ float Hs[16][64];
    __shared__ float Bsm[16][32];
    __shared__ float Gs[64][32];

    const float* __restrict__ hin = g_h[t & 1];
    float* __restrict__ hout = g_h[(t + 1) & 1];
    const float* __restrict__ gxt = g_gx + (size_t)t * BB * G4H;

    int tid = threadIdx.x;       // 256
    int jbase = blockIdx.x * 8;  // 128 blocks

    int tx = tid & 31;  // rows m0 = tx*2
    int ty = tid >> 5;  // cols = ty*4 (within 32 local gate cols)
    float acc[2][4] = {{0.f, 0.f, 0.f, 0.f}, {0.f, 0.f, 0.f, 0.f}};

    int hm = tid >> 2, hk4 = (tid & 3) * 4;  // h stage: float4 each

    for (int k0 = 0; k0 < HH; k0 += 16) {
        float4 hv = *(const float4*)(hin + (size_t)hm * HH + k0 + hk4);
        Hs[hk4 + 0][hm] = hv.x; Hs[hk4 + 1][hm] = hv.y;
        Hs[hk4 + 2][hm] = hv.z; Hs[hk4 + 3][hm] = hv.w;
#pragma unroll
        for (int r = 0; r < 2; r++) {
            int e = tid + r * 256;           // 512 elems: Bsm[k][lc]
            int k = e >> 5, lc = e & 31;
            int gcol = (lc >> 3) * HH + jbase + (lc & 7);
            Bsm[k][lc] = g_wT[(size_t)(DD + k0 + k) * G4H + gcol];
        }
        __syncthreads();
#pragma unroll
        for (int k = 0; k < 16; k++) {
            float2 a = *(const float2*)&Hs[k][tx * 2];
            float4 b = *(const float4*)&Bsm[k][ty * 4];
            acc[0][0] += a.x * b.x; acc[0][1] += a.x * b.y;
            acc[0][2] += a.x * b.z; acc[0][3] += a.x * b.w;
            acc[1][0] += a.y * b.x; acc[1][1] += a.y * b.y;
            acc[1][2] += a.y * b.z; acc[1][3] += a.y * b.w;
        }
        __syncthreads();
    }

    // gates -> shared with Gx added
#pragma unroll
    for (int i = 0; i < 2; i++)
#pragma unroll
        for (int j = 0; j < 4; j++) {
            int m = tx * 2 + i, lc = ty * 4 + j;
            int gcol = (lc >> 3) * HH + jbase + (lc & 7);
            Gs[m][lc] = acc[i][j] + gxt[(size_t)m * G4H + gcol];
        }
    __syncthreads();

    // cell update: 64 rows x 8 cols = 512 items
#pragma unroll
    for (int r = 0; r < 2; r++) {
        int e = tid + r * 256;
        int m = e >> 3, u = e & 7;
        float gi = Gs[m][u];
        float gf = Gs[m][8 + u];
        float go = Gs[m][16 + u];
        float gg = Gs[m][24 + u];
        float si = 1.f / (1.f + expf(-gi));
        float sf = 1.f / (1.f + expf(-gf));
        float so = 1.f / (1.f + expf(-go));
        float tg = tanhf(gg);
        int j = jbase + u;
        float c = sf * g_c[m * HH + j] + si * tg;
        g_c[m * HH + j] = c;
        float h = so * tanhf(c);
        hout[m * HH + j] = h;
        outp[((size_t)m * SS + t) * HH + j] = h;  // outputs[b][t][j]
    }
}

// ---------------- tail: final (h, c) leaves if the output buffer expects them ----------------
__global__ void tail_kernel(float* __restrict__ dst, int nh, int nc) {
    int i = blockIdx.x * blockDim.x + threadIdx.x;
    if (i < nh) dst[OUT_MAIN + i] = g_h[0][i];          // final h (after 512 steps parity=0)
    if (i < nc) dst[OUT_MAIN + 65536 + i] = g_c[i];     // final c
}

// ---------------- launch ----------------
extern "C" void kernel_launch(void* const* d_in, const int* in_sizes, int n_in,
                              void* d_out, int out_size) {
    const float* x = nullptr;
    const float* W = nullptr;
    const float* bias = nullptr;
    for (int i = 0; i < n_in; i++) {
        if (in_sizes[i] == BB * SS * DD) x = (const float*)d_in[i];
        else if (in_sizes[i] == G4H * KW) W = (const float*)d_in[i];
        else if (in_sizes[i] == G4H) bias = (const float*)d_in[i];
    }
    float* out = (float*)d_out;

    init_kernel<<<64, 1024>>>();
    transpose_kernel<<<dim3(KW / 32, G4H / 32), dim3(32, 8)>>>(W);
    gemm_x_kernel<<<dim3(G4H / 128, (BB * SS) / 128), 256>>>(x, bias);

    for (int t = 0; t < SS; t++) {
        lstm_step_kernel<<<128, 256>>>(out, t);
    }

    if (out_size > OUT_MAIN) {
        int extra = out_size - OUT_MAIN;
        int nh = extra < 65536 ? extra : 65536;
        int nc = extra > 65536 ? (extra - 65536 < 65536 ? extra - 65536 : 65536) : 0;
        tail_kernel<<<64, 1024>>>(out, nh, nc);
    }
}

// round 2
// speedup vs baseline: 1.2713x; 1.2713x over previous
#include <cuda_runtime.h>
#include <cuda_bf16.h>
#include <math.h>

// Problem constants
#define BB 64
#define SS 512
#define DD 1024
#define HH 1024
#define G4H 4096          // 4*H
#define KW 2048           // D+H
#define OUT_MAIN 33554432 // B*S*H
#define NBLK 128
#define NTHR 256
#define KC 64             // k-chunk for h streaming

// ---------------- device scratch (no allocs allowed) ----------------
__device__ float g_gx[(size_t)SS * BB * G4H];   // [s][b][4H]
__device__ float g_wT[(size_t)KW * G4H];        // W^T: [D+H][4H]
__device__ float g_hT[2][HH * BB];              // h transposed: [H][B], double buffered
__device__ float g_hfin[BB * HH];               // final h, [B][H]
__device__ float g_cfin[BB * HH];               // final c, [B][H]
__device__ unsigned g_arrive;
__device__ unsigned g_epoch;

// ---------------- init: zero h0 ----------------
__global__ void init_kernel() {
    int i = blockIdx.x * blockDim.x + threadIdx.x;
    if (i < HH * BB) g_hT[0][i] = 0.f;
}

// ---------------- W transpose: W[4096][2048] -> g_wT[2048][4096] ----------------
__global__ __launch_bounds__(256) void transpose_kernel(const float* __restrict__ W) {
    __shared__ float tile[32][33];
    int c0 = blockIdx.x * 32;
    int r0 = blockIdx.y * 32;
    int tx = threadIdx.x, ty = threadIdx.y;  // 32 x 8
#pragma unroll
    for (int i = 0; i < 32; i += 8)
        tile[ty + i][tx] = W[(size_t)(r0 + ty + i) * KW + c0 + tx];
    __syncthreads();
#pragma unroll
    for (int i = 0; i < 32; i += 8)
        g_wT[(size_t)(c0 + ty + i) * G4H + r0 + tx] = tile[tx][ty + i];
}

// ---------------- big GEMM: Gx = X[32768x1024] @ wT[0:1024][4096] + bias ----------------
__global__ __launch_bounds__(256) void gemm_x_kernel(const float* __restrict__ X,
                                                     const float* __restrict__ bias) {
    __shared__ float As[2][8][128];
    __shared__ float Bs[2][8][128];
    int tid = threadIdx.x;
    int bn = blockIdx.x;
    int bm = blockIdx.y;
    const float* Ab = X + (size_t)bm * 128 * DD;

    int arow = tid >> 1, ak = (tid & 1) * 4;
    int bk = tid >> 5, bcol = (tid & 31) * 4;

    float acc[8][8];
#pragma unroll
    for (int i = 0; i < 8; i++)
#pragma unroll
        for (int j = 0; j < 8; j++) acc[i][j] = 0.f;

    float4 av = *(const float4*)(Ab + (size_t)arow * DD + ak);
    float4 bv = *(const float4*)(g_wT + (size_t)bk * G4H + bn * 128 + bcol);
    As[0][ak + 0][arow] = av.x; As[0][ak + 1][arow] = av.y;
    As[0][ak + 2][arow] = av.z; As[0][ak + 3][arow] = av.w;
    *(float4*)&Bs[0][bk][bcol] = bv;
    __syncthreads();

    int buf = 0;
    int tx = tid & 15, ty = tid >> 4;

    for (int k0 = 0; k0 < DD; k0 += 8) {
        bool more = (k0 + 8) < DD;
        if (more) {
            av = *(const float4*)(Ab + (size_t)arow * DD + k0 + 8 + ak);
            bv = *(const float4*)(g_wT + (size_t)(k0 + 8 + bk) * G4H + bn * 128 + bcol);
        }
#pragma unroll
        for (int k = 0; k < 8; k++) {
            float a[8], b[8];
            *(float4*)&a[0] = *(const float4*)&As[buf][k][ty * 8];
            *(float4*)&a[4] = *(const float4*)&As[buf][k][ty * 8 + 4];
            *(float4*)&b[0] = *(const float4*)&Bs[buf][k][tx * 8];
            *(float4*)&b[4] = *(const float4*)&Bs[buf][k][tx * 8 + 4];
#pragma unroll
            for (int i = 0; i < 8; i++)
#pragma unroll
                for (int j = 0; j < 8; j++) acc[i][j] += a[i] * b[j];
        }
        if (more) {
            buf ^= 1;
            As[buf][ak + 0][arow] = av.x; As[buf][ak + 1][arow] = av.y;
            As[buf][ak + 2][arow] = av.z; As[buf][ak + 3][arow] = av.w;
            *(float4*)&Bs[buf][bk][bcol] = bv;
        }
        __syncthreads();
    }

    int ncol = bn * 128 + tx * 8;
    float4 bi0 = *(const float4*)(bias + ncol);
    float4 bi1 = *(const float4*)(bias + ncol + 4);
#pragma unroll
    for (int i = 0; i < 8; i++) {
        int r = bm * 128 + ty * 8 + i;
        int s = r & 511, b_ = r >> 9;
        size_t off = (size_t)(s * BB + b_) * G4H + ncol;
        float4 v0, v1;
        v0.x = acc[i][0] + bi0.x; v0.y = acc[i][1] + bi0.y;
        v0.z = acc[i][2] + bi0.z; v0.w = acc[i][3] + bi0.w;
        v1.x = acc[i][4] + bi1.x; v1.y = acc[i][5] + bi1.y;
        v1.z = acc[i][6] + bi1.z; v1.w = acc[i][7] + bi1.w;
        *(float4*)(g_gx + off) = v0;
        *(float4*)(g_gx + off + 4) = v1;
    }
}

// ---------------- grid barrier (all NBLK blocks resident) ----------------
__device__ __forceinline__ void grid_bar() {
    __syncthreads();
    if (threadIdx.x == 0) {
        __threadfence();
        unsigned e = g_epoch;  // epoch cannot advance until this block arrives
        unsigned old = atomicAdd(&g_arrive, 1);
        if (old == NBLK - 1) {
            g_arrive = 0;
            __threadfence();
            atomicExch(&g_epoch, e + 1);
        } else {
            while (*(volatile unsigned*)&g_epoch == e) {}
            __threadfence();
        }
    }
    __syncthreads();
}

// ---------------- persistent recurrent kernel ----------------
// 128 blocks, each owns 8 H-columns -> 32 gate columns, for all 512 steps.
// SMEM: Ws[1024][32] (128KB, resident), Hs double-buffered chunks, Gs exchange, Cs cell state.
__global__ __launch_bounds__(NTHR, 1) void lstm_persist(float* __restrict__ outp) {
    extern __shared__ float smem[];
    float* Ws = smem;                 // 1024*32 = 32768
    float* Hs = Ws + 32768;           // 2 * KC * 64 = 8192
    float* Gs = Hs + 8192;            // 64*33 = 2112
    float* Cs = Gs + 2112;            // 64*8 = 512

    int tid = threadIdx.x;
    int jb = blockIdx.x * 8;

    // load recurrent weight slice: Ws[k][lc], lc = gate*8 + u -> gcol = gate*1024 + jb + u
    for (int idx = tid; idx < 32768; idx += NTHR) {
        int k = idx >> 5, lc = idx & 31;
        int gcol = (lc >> 3) * HH + jb + (lc & 7);
        Ws[idx] = g_wT[(size_t)(DD + k) * G4H + gcol];
    }
    for (int idx = tid; idx < 512; idx += NTHR) Cs[idx] = 0.f;
    __syncthreads();

    int lane = tid & 31, warp = tid >> 5;
    int m = (warp & 1) * 32 + lane;   // batch row
    int ng = warp >> 2 == 0 ? warp >> 1 : warp >> 1;  // gate group 0..3
    ng = warp >> 1;
    int eu = tid & 7, em = tid >> 3;  // elementwise ids (round 0); round 1 adds 256

    for (int t = 0; t < SS; t++) {
        const float* __restrict__ hin = g_hT[t & 1];
        float* __restrict__ hout = g_hT[(t + 1) & 1];
        const float* __restrict__ gxt = g_gx + (size_t)t * BB * G4H;

        // prefetch Gx for (m, ng)
        const float* gp = gxt + (size_t)m * G4H + ng * HH + jb;
        float4 gx0 = *(const float4*)(gp);
        float4 gx1 = *(const float4*)(gp + 4);

        float acc[8];
#pragma unroll
        for (int j = 0; j < 8; j++) acc[j] = 0.f;

        // prologue: chunk 0 -> Hs[0]
        float4 pf[4];
#pragma unroll
        for (int i = 0; i < 4; i++)
            pf[i] = *(const float4*)(hin + tid * 16 + i * 4);
        int buf = 0;
#pragma unroll
        for (int i = 0; i < 4; i++)
            *(float4*)(Hs + tid * 16 + i * 4) = pf[i];
        __syncthreads();

        for (int c = 0; c < HH / KC; c++) {
            if (c < HH / KC - 1) {
#pragma unroll
                for (int i = 0; i < 4; i++)
                    pf[i] = *(const float4*)(hin + (c + 1) * (KC * BB) + tid * 16 + i * 4);
            }
            const float* __restrict__ H = Hs + buf * (KC * BB);
            const float* __restrict__ Wk = Ws + (c * KC) * 32;
#pragma unroll 16
            for (int k = 0; k < KC; k++) {
                float a = H[k * BB + m];
                float4 b0 = *(const float4*)(Wk + k * 32 + ng * 8);
                float4 b1 = *(const float4*)(Wk + k * 32 + ng * 8 + 4);
                acc[0] += a * b0.x; acc[1] += a * b0.y;
                acc[2] += a * b0.z; acc[3] += a * b0.w;
                acc[4] += a * b1.x; acc[5] += a * b1.y;
                acc[6] += a * b1.z; acc[7] += a * b1.w;
            }
            if (c < HH / KC - 1) {
                buf ^= 1;
#pragma unroll
                for (int i = 0; i < 4; i++)
                    *(float4*)(Hs + buf * (KC * BB) + tid * 16 + i * 4) = pf[i];
            }
            __syncthreads();
        }

        // dump gates (+Gx) to Gs[m][lc], lc = ng*8 + j, row stride 33 (pad)
        float* gr = Gs + m * 33 + ng * 8;
        gr[0] = acc[0] + gx0.x; gr[1] = acc[1] + gx0.y;
        gr[2] = acc[2] + gx0.z; gr[3] = acc[3] + gx0.w;
        gr[4] = acc[4] + gx1.x; gr[5] = acc[5] + gx1.y;
        gr[6] = acc[6] + gx1.z; gr[7] = acc[7] + gx1.w;
        __syncthreads();

        // cell update: 512 items = 64 m x 8 u
#pragma unroll
        for (int r = 0; r < 2; r++) {
            int e = tid + r * NTHR;
            int mm = e >> 3, u = e & 7;
            float gi = Gs[mm * 33 + u];
            float gf = Gs[mm * 33 + 8 + u];
            float go = Gs[mm * 33 + 16 + u];
            float gg = Gs[mm * 33 + 24 + u];
            float si = 1.f / (1.f + __expf(-gi));
            float sf = 1.f / (1.f + __expf(-gf));
            float so = 1.f / (1.f + __expf(-go));
            float tg = tanhf(gg);
            float cn = sf * Cs[mm * 8 + u] + si * tg;
            Cs[mm * 8 + u] = cn;
            float h = so * tanhf(cn);
            hout[(size_t)(jb + u) * BB + mm] = h;
            outp[((size_t)mm * SS + t) * HH + jb + u] = h;
            if (t == SS - 1) {
                g_hfin[(size_t)mm * HH + jb + u] = h;
                g_cfin[(size_t)mm * HH + jb + u] = cn;
            }
        }
        grid_bar();
    }
}

// ---------------- tail: final (h, c) leaves if present ----------------
__global__ void tail_kernel(float* __restrict__ dst, int nh, int nc) {
    int i = blockIdx.x * blockDim.x + threadIdx.x;
    if (i < nh) dst[OUT_MAIN + i] = g_hfin[i];
    if (i < nc) dst[OUT_MAIN + 65536 + i] = g_cfin[i];
}

// ---------------- launch ----------------
extern "C" void kernel_launch(void* const* d_in, const int* in_sizes, int n_in,
                              void* d_out, int out_size) {
    const float* x = nullptr;
    const float* W = nullptr;
    const float* bias = nullptr;
    for (int i = 0; i < n_in; i++) {
        if (in_sizes[i] == BB * SS * DD) x = (const float*)d_in[i];
        else if (in_sizes[i] == G4H * KW) W = (const float*)d_in[i];
        else if (in_sizes[i] == G4H) bias = (const float*)d_in[i];
    }
    float* out = (float*)d_out;

    static int smem_set = 0;
    int smem_bytes = (32768 + 8192 + 2112 + 512) * 4;  // 174336
    if (!smem_set) {
        cudaFuncSetAttribute(lstm_persist, cudaFuncAttributeMaxDynamicSharedMemorySize,
                             smem_bytes);
        smem_set = 1;
    }

    init_kernel<<<64, 1024>>>();
    transpose_kernel<<<dim3(KW / 32, G4H / 32), dim3(32, 8)>>>(W);
    gemm_x_kernel<<<dim3(G4H / 128, (BB * SS) / 128), 256>>>(x, bias);

    lstm_persist<<<NBLK, NTHR, smem_bytes>>>(out);

    if (out_size > OUT_MAIN) {
        int extra = out_size - OUT_MAIN;
        int nh = extra < 65536 ? extra : 65536;
        int nc = extra > 65536 ? (extra - 65536 < 65536 ? extra - 65536 : 65536) : 0;
        tail_kernel<<<64, 1024>>>(out, nh, nc);
    }
}

// round 4
// speedup vs baseline: 1.5903x; 1.2509x over previous
#include <cuda_runtime.h>
#include <cuda_bf16.h>
#include <math.h>
#include <stdint.h>

// Problem constants
#define BB 64
#define SS 512
#define DD 1024
#define HH 1024
#define G4H 4096          // 4*H
#define KW 2048           // D+H
#define KP 3072           // split-bf16 packed K (hi|hi|lo)
#define OUT_MAIN 33554432 // B*S*H
#define NBLK 128
#define NTHR 256
#define KC 64             // k-chunk for h streaming (persist kernel)

// tcgen05 availability: only in the arch-specific (sm_103a/sm_100a) compile pass.
#if defined(__CUDA_ARCH_FEAT_SM103_ALL) || defined(__CUDA_ARCH_FEAT_SM100_ALL) || \
    (defined(__CUDA_ARCH_SPECIFIC__) && (__CUDA_ARCH_SPECIFIC__ >= 1000))
#define HAS_TC5 1
#else
#define HAS_TC5 0
#endif

// ---------------- device scratch (no allocs allowed) ----------------
__device__ float g_gx[(size_t)SS * BB * G4H];         // [s][b][4H]
__device__ float g_wT[(size_t)KW * G4H];              // W^T: [D+H][4H] (persist uses rows DD..)
__device__ __nv_bfloat16 g_a[(size_t)(BB * SS) * KP]; // A' split-bf16 [32768][3072]
__device__ __nv_bfloat16 g_b[(size_t)G4H * KP];       // B' split-bf16 [4096][3072]
__device__ float g_hT[2][HH * BB];
__device__ float g_hfin[BB * HH];
__device__ float g_cfin[BB * HH];
__device__ unsigned g_arrive;
__device__ unsigned g_epoch;

// ---------------- PTX helpers ----------------
__device__ __forceinline__ uint32_t smem_u32(const void* p) {
    uint32_t a;
    asm("{ .reg .u64 t; cvta.to.shared.u64 t, %1; cvt.u32.u64 %0, t; }" : "=r"(a) : "l"(p));
    return a;
}

#if HAS_TC5
__device__ __forceinline__ uint32_t elect1() {
    uint32_t p;
    asm volatile("{\n\t.reg .pred p;\n\telect.sync _|p, 0xFFFFFFFF;\n\tselp.b32 %0, 1, 0, p;\n\t}" : "=r"(p));
    return p;
}
__device__ __forceinline__ void mbar_init(uint32_t mbar, uint32_t cnt) {
    asm volatile("mbarrier.init.shared.b64 [%0], %1;" :: "r"(mbar), "r"(cnt) : "memory");
}
__device__ __forceinline__ void mbar_wait(uint32_t mbar, uint32_t parity) {
    asm volatile(
        "{\n\t.reg .pred P1;\n\t"
        "WL%=:\n\t"
        "mbarrier.try_wait.parity.acquire.cta.shared::cta.b64 P1, [%0], %1, 0x989680;\n\t"
        "@P1 bra.uni WD%=;\n\t"
        "bra.uni WL%=;\n\t"
        "WD%=:\n\t}"
        :: "r"(mbar), "r"(parity) : "memory");
}
__device__ __forceinline__ void mma_f16_ss(uint32_t d, uint64_t ad, uint64_t bd,
                                           uint32_t idesc, uint32_t en) {
    asm volatile(
        "{\n\t.reg .pred p;\n\tsetp.ne.u32 p, %5, 0;\n\t"
        "tcgen05.mma.cta_group::1.kind::f16 [%0], %1, %2, %3, {%4, %4, %4, %4}, p;\n\t}"
        :: "r"(d), "l"(ad), "l"(bd), "r"(idesc), "r"(0u), "r"(en) : "memory");
}
__device__ __forceinline__ void tc_commit(uint32_t mbar) {
    asm volatile("tcgen05.commit.cta_group::1.mbarrier::arrive::one.shared::cluster.b64 [%0];"
                 :: "r"(mbar) : "memory");
}
#define LDTM_X32(r, addr) \
    asm volatile( \
        "tcgen05.ld.sync.aligned.32x32b.x32.b32 " \
        "{%0, %1, %2, %3, %4, %5, %6, %7, %8, %9, %10, %11, %12, %13, %14, %15, " \
        " %16, %17, %18, %19, %20, %21, %22, %23, %24, %25, %26, %27, %28, %29, %30, %31}, [%32];" \
        : "=r"((r)[0]), "=r"((r)[1]), "=r"((r)[2]), "=r"((r)[3]), \
          "=r"((r)[4]), "=r"((r)[5]), "=r"((r)[6]), "=r"((r)[7]), \
          "=r"((r)[8]), "=r"((r)[9]), "=r"((r)[10]), "=r"((r)[11]), \
          "=r"((r)[12]), "=r"((r)[13]), "=r"((r)[14]), "=r"((r)[15]), \
          "=r"((r)[16]), "=r"((r)[17]), "=r"((r)[18]), "=r"((r)[19]), \
          "=r"((r)[20]), "=r"((r)[21]), "=r"((r)[22]), "=r"((r)[23]), \
          "=r"((r)[24]), "=r"((r)[25]), "=r"((r)[26]), "=r"((r)[27]), \
          "=r"((r)[28]), "=r"((r)[29]), "=r"((r)[30]), "=r"((r)[31]) \
        : "r"(addr))
#endif  // HAS_TC5

static constexpr uint64_t DESC_BASE_SW128 =
    (2ULL << 61) | (1ULL << 46) | (64ULL << 32) | (1ULL << 16);
#define MK_DESC(a) (DESC_BASE_SW128 | (((uint64_t)((a) >> 4)) & 0x3FFF))
#define SWZ(o) ((o) ^ (((o) >> 3) & 0x70))

// idesc: kind::f16, dtype=F32, a/b=BF16, M=128, N=256
#define GEMM_IDESC ((1u << 4) | (1u << 7) | (1u << 10) | ((256u / 8u) << 17) | ((128u / 16u) << 24))

// ---------------- init: zero h0 ----------------
__global__ void init_kernel() {
    int i = blockIdx.x * blockDim.x + threadIdx.x;
    if (i < HH * BB) g_hT[0][i] = 0.f;
}

// ---------------- W transpose (for recurrent part): W[4096][2048] -> g_wT[2048][4096] ---
__global__ __launch_bounds__(256) void transpose_kernel(const float* __restrict__ W) {
    __shared__ float tile[32][33];
    int c0 = blockIdx.x * 32;
    int r0 = blockIdx.y * 32;
    int tx = threadIdx.x, ty = threadIdx.y;
#pragma unroll
    for (int i = 0; i < 32; i += 8)
        tile[ty + i][tx] = W[(size_t)(r0 + ty + i) * KW + c0 + tx];
    __syncthreads();
#pragma unroll
    for (int i = 0; i < 32; i += 8)
        g_wT[(size_t)(c0 + ty + i) * G4H + r0 + tx] = tile[tx][ty + i];
}

// ---------------- split-bf16 conversion ----------------
__device__ __forceinline__ void split4(float4 v, uint2& hq, uint2& lq) {
    __nv_bfloat16 h0 = __float2bfloat16(v.x), h1 = __float2bfloat16(v.y);
    __nv_bfloat16 h2 = __float2bfloat16(v.z), h3 = __float2bfloat16(v.w);
    __nv_bfloat16 l0 = __float2bfloat16(v.x - __bfloat162float(h0));
    __nv_bfloat16 l1 = __float2bfloat16(v.y - __bfloat162float(h1));
    __nv_bfloat16 l2 = __float2bfloat16(v.z - __bfloat162float(h2));
    __nv_bfloat16 l3 = __float2bfloat16(v.w - __bfloat162float(h3));
    hq.x = (uint32_t)__bfloat16_as_ushort(h0) | ((uint32_t)__bfloat16_as_ushort(h1) << 16);
    hq.y = (uint32_t)__bfloat16_as_ushort(h2) | ((uint32_t)__bfloat16_as_ushort(h3) << 16);
    lq.x = (uint32_t)__bfloat16_as_ushort(l0) | ((uint32_t)__bfloat16_as_ushort(l1) << 16);
    lq.y = (uint32_t)__bfloat16_as_ushort(l2) | ((uint32_t)__bfloat16_as_ushort(l3) << 16);
}

// A' = [hi | hi | lo] from x [32768][1024]
__global__ __launch_bounds__(256) void conv_a_kernel(const float* __restrict__ x) {
    int gid = blockIdx.x * 256 + threadIdx.x;
    int m = gid >> 8;
    int kq = (gid & 255) << 2;
    float4 v = *(const float4*)(x + (size_t)m * DD + kq);
    uint2 hq, lq;
    split4(v, hq, lq);
    char* base = (char*)(g_a + (size_t)m * KP + kq);
    *(uint2*)(base) = hq;
    *(uint2*)(base + 1024 * 2) = hq;
    *(uint2*)(base + 2048 * 2) = lq;
}

// B' = [hi | lo | hi] from W rows [4096][2048], x-part cols 0..1023
__global__ __launch_bounds__(256) void conv_b_kernel(const float* __restrict__ W) {
    int gid = blockIdx.x * 256 + threadIdx.x;
    int n = gid >> 8;
    int kq = (gid & 255) << 2;
    float4 v = *(const float4*)(W + (size_t)n * KW + kq);
    uint2 hq, lq;
    split4(v, hq, lq);
    char* base = (char*)(g_b + (size_t)n * KP + kq);
    *(uint2*)(base) = hq;
    *(uint2*)(base + 1024 * 2) = lq;
    *(uint2*)(base + 2048 * 2) = hq;
}

// ---------------- tcgen05 x-GEMM: Gx = A'[32768xKP] . B'[4096xKP]^T + bias --------
// CTA tile 128x256, K stage 64, 48 stages, double-buffered, 2 CTAs/SM.
#define OF_A 1024
#define OF_B 33792
#define GEMM_SMEM (33792 + 2 * 32768)
__global__ __launch_bounds__(256, 2) void gemm_tc(const float* __restrict__ bias) {
#if HAS_TC5
    extern __shared__ __align__(1024) char smem[];
    uint32_t sbase = smem_u32(smem);
    int tid = threadIdx.x;
    int wid = tid >> 5, lane = tid & 31;
    int bn = blockIdx.x;  // 0..15
    int bm = blockIdx.y;  // 0..255

    if (wid == 0) {
        asm volatile("tcgen05.alloc.cta_group::1.sync.aligned.shared::cta.b32 [%0], %1;"
                     :: "r"(sbase), "r"(256) : "memory");
        asm volatile("tcgen05.relinquish_alloc_permit.cta_group::1.sync.aligned;");
    }
    if (tid == 0) {
        mbar_init(sbase + 8, 1);
        mbar_init(sbase + 16, 1);
    }
    __syncthreads();
    uint32_t tmem;
    asm volatile("ld.shared.b32 %0, [%1];" : "=r"(tmem) : "r"(sbase));

    const __nv_bfloat16* Ab = g_a + (size_t)(bm * 128) * KP;
    const __nv_bfloat16* Bb = g_b + (size_t)(bn * 256) * KP;

    uint4 ra[4], rb[8];

#define LOAD_STAGE(k0)                                                                  \
    do {                                                                                \
        _Pragma("unroll") for (int i = 0; i < 4; i++) {                                 \
            int ch = tid + i * 256;                                                     \
            ra[i] = *(const uint4*)(Ab + (size_t)(ch >> 3) * KP + (k0) + (ch & 7) * 8); \
        }                                                                               \
        _Pragma("unroll") for (int i = 0; i < 8; i++) {                                 \
            int ch = tid + i * 256;                                                     \
            rb[i] = *(const uint4*)(Bb + (size_t)(ch >> 3) * KP + (k0) + (ch & 7) * 8); \
        }                                                                               \
    } while (0)

#define STORE_STAGE(buf)                                                     \
    do {                                                                     \
        _Pragma("unroll") for (int i = 0; i < 4; i++) {                      \
            int ch = tid + i * 256;                                          \
            uint32_t off = (uint32_t)(ch >> 3) * 128 + (ch & 7) * 16;        \
            *(uint4*)(smem + OF_A + (buf) * 16384 + SWZ(off)) = ra[i];       \
        }                                                                    \
        _Pragma("unroll") for (int i = 0; i < 8; i++) {                      \
            int ch = tid + i * 256;                                          \
            uint32_t off = (uint32_t)(ch >> 3) * 128 + (ch & 7) * 16;        \
            *(uint4*)(smem + OF_B + (buf) * 32768 + SWZ(off)) = rb[i];       \
        }                                                                    \
    } while (0)

    LOAD_STAGE(0);
    for (int s = 0; s < 48; s++) {
        int buf = s & 1;
        if (s >= 2) mbar_wait(sbase + 8 + buf * 8, ((s >> 1) & 1) ^ 1);
        STORE_STAGE(buf);
        __syncthreads();
        if (wid == 0) {
            asm volatile("fence.proxy.async.shared::cta;" ::: "memory");
            if (elect1()) {
                uint64_t ad = MK_DESC(sbase + OF_A + buf * 16384);
                uint64_t bd = MK_DESC(sbase + OF_B + buf * 32768);
#pragma unroll
                for (int k = 0; k < 4; k++)
                    mma_f16_ss(tmem, ad + k * 2, bd + k * 2, GEMM_IDESC,
                               (s > 0 || k > 0) ? 1u : 0u);
                tc_commit(sbase + 8 + buf * 8);
            }
        }
        if (s + 1 < 48) LOAD_STAGE((s + 1) * 64);
    }
    mbar_wait(sbase + 8, 1);
    mbar_wait(sbase + 16, 1);
    asm volatile("tcgen05.fence::after_thread_sync;" ::: "memory");

    if (wid < 4) {
        int m = bm * 128 + wid * 32 + lane;
        int s_ = m & 511, b_ = m >> 9;
        float* orow = g_gx + (size_t)(s_ * BB + b_) * G4H + bn * 256;
        const float* brow = bias + bn * 256;
#pragma unroll 1
        for (int cb = 0; cb < 256; cb += 32) {
            uint32_t r[32];
            LDTM_X32(r, tmem + cb);
            asm volatile("tcgen05.wait::ld.sync.aligned;" ::: "memory");
#pragma unroll
            for (int j = 0; j < 32; j += 4) {
                float4 v;
                v.x = __uint_as_float(r[j + 0]) + __ldg(brow + cb + j + 0);
                v.y = __uint_as_float(r[j + 1]) + __ldg(brow + cb + j + 1);
                v.z = __uint_as_float(r[j + 2]) + __ldg(brow + cb + j + 2);
                v.w = __uint_as_float(r[j + 3]) + __ldg(brow + cb + j + 3);
                *(float4*)(orow + cb + j) = v;
            }
        }
    }
    __syncthreads();
    if (wid == 0) {
        asm volatile("tcgen05.dealloc.cta_group::1.sync.aligned.b32 %0, %1;"
                     :: "r"(tmem), "r"(256));
    }
#else
    // SIMT fallback for the non-arch-specific PTX pass (never selected on GB300:
    // the sm_103a cubin is preferred). Computes the same split-bf16 product.
    int tid = threadIdx.x;
    int bn = blockIdx.x, bm = blockIdx.y;
    for (int idx = tid; idx < 128 * 256; idx += 256) {
        int mi = idx >> 8, ni = idx & 255;
        int m = bm * 128 + mi, n = bn * 256 + ni;
        const __nv_bfloat16* ar = g_a + (size_t)m * KP;
        const __nv_bfloat16* br = g_b + (size_t)n * KP;
        float acc = 0.f;
        for (int k = 0; k < KP; k += 2) {
            __nv_bfloat162 av = *(const __nv_bfloat162*)(ar + k);
            __nv_bfloat162 bv = *(const __nv_bfloat162*)(br + k);
            acc += __bfloat162float(av.x) * __bfloat162float(bv.x);
            acc += __bfloat162float(av.y) * __bfloat162float(bv.y);
        }
        int s_ = m & 511, b_ = m >> 9;
        g_gx[(size_t)(s_ * BB + b_) * G4H + n] = acc + bias[n];
    }
#endif
}

// ---------------- grid barrier ----------------
__device__ __forceinline__ void grid_bar() {
    __syncthreads();
    if (threadIdx.x == 0) {
        __threadfence();
        unsigned e = g_epoch;
        unsigned old = atomicAdd(&g_arrive, 1);
        if (old == NBLK - 1) {
            g_arrive = 0;
            __threadfence();
            atomicExch(&g_epoch, e + 1);
        } else {
            while (*(volatile unsigned*)&g_epoch == e) {}
            __threadfence();
        }
    }
    __syncthreads();
}

// ---------------- persistent recurrent kernel ----------------
__global__ __launch_bounds__(NTHR, 1) void lstm_persist(float* __restrict__ outp) {
    extern __shared__ float fsm[];
    float* Ws = fsm;
    float* Hs = Ws + 32768;
    float* Gs = Hs + 8192;
    float* Cs = Gs + 2112;

    int tid = threadIdx.x;
    int jb = blockIdx.x * 8;

    for (int idx = tid; idx < 32768; idx += NTHR) {
        int k = idx >> 5, lc = idx & 31;
        int gcol = (lc >> 3) * HH + jb + (lc & 7);
        Ws[idx] = g_wT[(size_t)(DD + k) * G4H + gcol];
    }
    for (int idx = tid; idx < 512; idx += NTHR) Cs[idx] = 0.f;
    __syncthreads();

    int lane = tid & 31, warp = tid >> 5;
    int m = (warp & 1) * 32 + lane;
    int ng = warp >> 1;

    for (int t = 0; t < SS; t++) {
        const float* __restrict__ hin = g_hT[t & 1];
        float* __restrict__ hout = g_hT[(t + 1) & 1];
        const float* __restrict__ gxt = g_gx + (size_t)t * BB * G4H;

        const float* gp = gxt + (size_t)m * G4H + ng * HH + jb;
        float4 gx0 = *(const float4*)(gp);
        float4 gx1 = *(const float4*)(gp + 4);

        float acc[8];
#pragma unroll
        for (int j = 0; j < 8; j++) acc[j] = 0.f;

        float4 pf[4];
#pragma unroll
        for (int i = 0; i < 4; i++) pf[i] = *(const float4*)(hin + tid * 16 + i * 4);
        int buf = 0;
#pragma unroll
        for (int i = 0; i < 4; i++) *(float4*)(Hs + tid * 16 + i * 4) = pf[i];
        __syncthreads();

        for (int c = 0; c < HH / KC; c++) {
            if (c < HH / KC - 1) {
#pragma unroll
                for (int i = 0; i < 4; i++)
                    pf[i] = *(const float4*)(hin + (c + 1) * (KC * BB) + tid * 16 + i * 4);
            }
            const float* __restrict__ H = Hs + buf * (KC * BB);
            const float* __restrict__ Wk = Ws + (c * KC) * 32;
#pragma unroll 16
            for (int k = 0; k < KC; k++) {
                float a = H[k * BB + m];
                float4 b0 = *(const float4*)(Wk + k * 32 + ng * 8);
                float4 b1 = *(const float4*)(Wk + k * 32 + ng * 8 + 4);
                acc[0] += a * b0.x; acc[1] += a * b0.y;
                acc[2] += a * b0.z; acc[3] += a * b0.w;
                acc[4] += a * b1.x; acc[5] += a * b1.y;
                acc[6] += a * b1.z; acc[7] += a * b1.w;
            }
            if (c < HH / KC - 1) {
                buf ^= 1;
#pragma unroll
                for (int i = 0; i < 4; i++)
                    *(float4*)(Hs + buf * (KC * BB) + tid * 16 + i * 4) = pf[i];
            }
            __syncthreads();
        }

        float* gr = Gs + m * 33 + ng * 8;
        gr[0] = acc[0] + gx0.x; gr[1] = acc[1] + gx0.y;
        gr[2] = acc[2] + gx0.z; gr[3] = acc[3] + gx0.w;
        gr[4] = acc[4] + gx1.x; gr[5] = acc[5] + gx1.y;
        gr[6] = acc[6] + gx1.z; gr[7] = acc[7] + gx1.w;
        __syncthreads();

#pragma unroll
        for (int r = 0; r < 2; r++) {
            int e = tid + r * NTHR;
            int mm = e >> 3, u = e & 7;
            float gi = Gs[mm * 33 + u];
            float gf = Gs[mm * 33 + 8 + u];
            float go = Gs[mm * 33 + 16 + u];
            float gg = Gs[mm * 33 + 24 + u];
            float si = 1.f / (1.f + __expf(-gi));
            float sf = 1.f / (1.f + __expf(-gf));
            float so = 1.f / (1.f + __expf(-go));
            float tg = tanhf(gg);
            float cn = sf * Cs[mm * 8 + u] + si * tg;
            Cs[mm * 8 + u] = cn;
            float h = so * tanhf(cn);
            hout[(size_t)(jb + u) * BB + mm] = h;
            outp[((size_t)mm * SS + t) * HH + jb + u] = h;
            if (t == SS - 1) {
                g_hfin[(size_t)mm * HH + jb + u] = h;
                g_cfin[(size_t)mm * HH + jb + u] = cn;
            }
        }
        grid_bar();
    }
}

// ---------------- tail: final (h, c) leaves if present ----------------
__global__ void tail_kernel(float* __restrict__ dst, int nh, int nc) {
    int i = blockIdx.x * blockDim.x + threadIdx.x;
    if (i < nh) dst[OUT_MAIN + i] = g_hfin[i];
    if (i < nc) dst[OUT_MAIN + 65536 + i] = g_cfin[i];
}

// ---------------- launch ----------------
extern "C" void kernel_launch(void* const* d_in, const int* in_sizes, int n_in,
                              void* d_out, int out_size) {
    const float* x = nullptr;
    const float* W = nullptr;
    const float* bias = nullptr;
    for (int i = 0; i < n_in; i++) {
        if (in_sizes[i] == BB * SS * DD) x = (const float*)d_in[i];
        else if (in_sizes[i] == G4H * KW) W = (const float*)d_in[i];
        else if (in_sizes[i] == G4H) bias = (const float*)d_in[i];
    }
    float* out = (float*)d_out;

    int psmem = (32768 + 8192 + 2112 + 512) * 4;
    cudaFuncSetAttribute(lstm_persist, cudaFuncAttributeMaxDynamicSharedMemorySize, psmem);
    cudaFuncSetAttribute(gemm_tc, cudaFuncAttributeMaxDynamicSharedMemorySize, GEMM_SMEM);

    init_kernel<<<64, 1024>>>();
    transpose_kernel<<<dim3(KW / 32, G4H / 32), dim3(32, 8)>>>(W);
    conv_a_kernel<<<(BB * SS * 256) / 256, 256>>>(x);
    conv_b_kernel<<<(G4H * 256) / 256, 256>>>(W);

    gemm_tc<<<dim3(16, 256), 256, GEMM_SMEM>>>(bias);

    lstm_persist<<<NBLK, NTHR, psmem>>>(out);

    if (out_size > OUT_MAIN) {
        int extra = out_size - OUT_MAIN;
        int nh = extra < 65536 ? extra : 65536;
        int nc = extra > 65536 ? (extra - 65536 < 65536 ? extra - 65536 : 65536) : 0;
        tail_kernel<<<64, 1024>>>(out, nh, nc);
    }
}

// round 6
// speedup vs baseline: 2.3073x; 1.4509x over previous
#include <cuda_runtime.h>
#include <cuda_bf16.h>
#include <math.h>
#include <stdint.h>

// Problem constants
#define BB 64
#define SS 512
#define DD 1024
#define HH 1024
#define G4H 4096          // 4*H
#define KW 2048           // D+H
#define KP 3072           // split-bf16 packed K for x-GEMM (hi|hi|lo)
#define KHP2 2048         // packed h cols: [hi | lo]
#define OUT_MAIN 33554432 // B*S*H
#define RNBLK 128
#define RNTHR 256

// tcgen05 availability: only in the arch-specific (sm_103a/sm_100a) compile pass.
#if defined(__CUDA_ARCH_FEAT_SM103_ALL) || defined(__CUDA_ARCH_FEAT_SM100_ALL) || \
    (defined(__CUDA_ARCH_SPECIFIC__) && (__CUDA_ARCH_SPECIFIC__ >= 1000))
#define HAS_TC5 1
#else
#define HAS_TC5 0
#endif

// ---------------- device scratch (no allocs allowed) ----------------
__device__ float g_gx[(size_t)SS * BB * G4H];            // [s][b][4H]
__device__ __nv_bfloat16 g_a[(size_t)(BB * SS) * KP];    // A' split-bf16 [32768][3072]
__device__ __nv_bfloat16 g_b[(size_t)G4H * KP];          // B' split-bf16 [4096][3072]
__device__ __nv_bfloat16 g_bh[(size_t)RNBLK * 32 * KHP2];// Wh' [128*32][2048] = [Whi|Wlo]
__device__ __nv_bfloat16 g_hsp[2][(size_t)BB * KHP2];    // h' [b][2048] = [hi|lo], dbl buf
__device__ float g_hfin[BB * HH];
__device__ float g_cfin[BB * HH];
__device__ unsigned g_arrive;
__device__ unsigned g_epoch;

// ---------------- PTX helpers ----------------
__device__ __forceinline__ uint32_t smem_u32(const void* p) {
    uint32_t a;
    asm("{ .reg .u64 t; cvta.to.shared.u64 t, %1; cvt.u32.u64 %0, t; }" : "=r"(a) : "l"(p));
    return a;
}

#if HAS_TC5
__device__ __forceinline__ uint32_t elect1() {
    uint32_t p;
    asm volatile("{\n\t.reg .pred p;\n\telect.sync _|p, 0xFFFFFFFF;\n\tselp.b32 %0, 1, 0, p;\n\t}" : "=r"(p));
    return p;
}
__device__ __forceinline__ void mbar_init(uint32_t mbar, uint32_t cnt) {
    asm volatile("mbarrier.init.shared.b64 [%0], %1;" :: "r"(mbar), "r"(cnt) : "memory");
}
__device__ __forceinline__ void mbar_wait(uint32_t mbar, uint32_t parity) {
    asm volatile(
        "{\n\t.reg .pred P1;\n\t"
        "WL%=:\n\t"
        "mbarrier.try_wait.parity.acquire.cta.shared::cta.b64 P1, [%0], %1, 0x989680;\n\t"
        "@P1 bra.uni WD%=;\n\t"
        "bra.uni WL%=;\n\t"
        "WD%=:\n\t}"
        :: "r"(mbar), "r"(parity) : "memory");
}
__device__ __forceinline__ void mma_f16_ss(uint32_t d, uint64_t ad, uint64_t bd,
                                           uint32_t idesc, uint32_t en) {
    asm volatile(
        "{\n\t.reg .pred p;\n\tsetp.ne.u32 p, %5, 0;\n\t"
        "tcgen05.mma.cta_group::1.kind::f16 [%0], %1, %2, %3, {%4, %4, %4, %4}, p;\n\t}"
        :: "r"(d), "l"(ad), "l"(bd), "r"(idesc), "r"(0u), "r"(en) : "memory");
}
__device__ __forceinline__ void tc_commit(uint32_t mbar) {
    asm volatile("tcgen05.commit.cta_group::1.mbarrier::arrive::one.shared::cluster.b64 [%0];"
                 :: "r"(mbar) : "memory");
}
#define LDTM_X32(r, addr) \
    asm volatile( \
        "tcgen05.ld.sync.aligned.32x32b.x32.b32 " \
        "{%0, %1, %2, %3, %4, %5, %6, %7, %8, %9, %10, %11, %12, %13, %14, %15, " \
        " %16, %17, %18, %19, %20, %21, %22, %23, %24, %25, %26, %27, %28, %29, %30, %31}, [%32];" \
        : "=r"((r)[0]), "=r"((r)[1]), "=r"((r)[2]), "=r"((r)[3]), \
          "=r"((r)[4]), "=r"((r)[5]), "=r"((r)[6]), "=r"((r)[7]), \
          "=r"((r)[8]), "=r"((r)[9]), "=r"((r)[10]), "=r"((r)[11]), \
          "=r"((r)[12]), "=r"((r)[13]), "=r"((r)[14]), "=r"((r)[15]), \
          "=r"((r)[16]), "=r"((r)[17]), "=r"((r)[18]), "=r"((r)[19]), \
          "=r"((r)[20]), "=r"((r)[21]), "=r"((r)[22]), "=r"((r)[23]), \
          "=r"((r)[24]), "=r"((r)[25]), "=r"((r)[26]), "=r"((r)[27]), \
          "=r"((r)[28]), "=r"((r)[29]), "=r"((r)[30]), "=r"((r)[31]) \
        : "r"(addr))
#endif  // HAS_TC5

static constexpr uint64_t DESC_BASE_SW128 =
    (2ULL << 61) | (1ULL << 46) | (64ULL << 32) | (1ULL << 16);
#define MK_DESC(a) (DESC_BASE_SW128 | (((uint64_t)((a) >> 4)) & 0x3FFF))
#define SWZ(o) ((o) ^ (((o) >> 3) & 0x70))

// idesc: kind::f16, dtype=F32, a/b=BF16
#define GEMM_IDESC ((1u << 4) | (1u << 7) | (1u << 10) | ((256u / 8u) << 17) | ((128u / 16u) << 24))
// M=128, N=32 — identical to the validated test_mma.cu config (0x8080490)
#define REC_IDESC  ((1u << 4) | (1u << 7) | (1u << 10) | ((32u / 8u) << 17) | ((128u / 16u) << 24))

// ---------------- init: zero h0 packed buffer 0 ----------------
__global__ void init_kernel() {
    int i = blockIdx.x * blockDim.x + threadIdx.x;
    if (i < (BB * KHP2) / 2) ((uint32_t*)g_hsp[0])[i] = 0u;
}

// ---------------- split-bf16 conversion ----------------
__device__ __forceinline__ void split4(float4 v, uint2& hq, uint2& lq) {
    __nv_bfloat16 h0 = __float2bfloat16(v.x), h1 = __float2bfloat16(v.y);
    __nv_bfloat16 h2 = __float2bfloat16(v.z), h3 = __float2bfloat16(v.w);
    __nv_bfloat16 l0 = __float2bfloat16(v.x - __bfloat162float(h0));
    __nv_bfloat16 l1 = __float2bfloat16(v.y - __bfloat162float(h1));
    __nv_bfloat16 l2 = __float2bfloat16(v.z - __bfloat162float(h2));
    __nv_bfloat16 l3 = __float2bfloat16(v.w - __bfloat162float(h3));
    hq.x = (uint32_t)__bfloat16_as_ushort(h0) | ((uint32_t)__bfloat16_as_ushort(h1) << 16);
    hq.y = (uint32_t)__bfloat16_as_ushort(h2) | ((uint32_t)__bfloat16_as_ushort(h3) << 16);
    lq.x = (uint32_t)__bfloat16_as_ushort(l0) | ((uint32_t)__bfloat16_as_ushort(l1) << 16);
    lq.y = (uint32_t)__bfloat16_as_ushort(l2) | ((uint32_t)__bfloat16_as_ushort(l3) << 16);
}

// A' = [hi | hi | lo] from x [32768][1024]
__global__ __launch_bounds__(256) void conv_a_kernel(const float* __restrict__ x) {
    int gid = blockIdx.x * 256 + threadIdx.x;
    int m = gid >> 8;
    int kq = (gid & 255) << 2;
    float4 v = *(const float4*)(x + (size_t)m * DD + kq);
    uint2 hq, lq;
    split4(v, hq, lq);
    char* base = (char*)(g_a + (size_t)m * KP + kq);
    *(uint2*)(base) = hq;
    *(uint2*)(base + 1024 * 2) = hq;
    *(uint2*)(base + 2048 * 2) = lq;
}

// B' = [hi | lo | hi] from W rows [4096][2048], x-part cols 0..1023
__global__ __launch_bounds__(256) void conv_b_kernel(const float* __restrict__ W) {
    int gid = blockIdx.x * 256 + threadIdx.x;
    int n = gid >> 8;
    int kq = (gid & 255) << 2;
    float4 v = *(const float4*)(W + (size_t)n * KW + kq);
    uint2 hq, lq;
    split4(v, hq, lq);
    char* base = (char*)(g_b + (size_t)n * KP + kq);
    *(uint2*)(base) = hq;
    *(uint2*)(base + 1024 * 2) = lq;
    *(uint2*)(base + 2048 * 2) = hq;
}

// Wh' packed per recurrent CTA: row rp = cta*32 + gate*8 + u, [Whi | Wlo] (2048),
// source W rows n = gate*1024 + cta*8 + u, h-part cols 1024..2047.
__global__ __launch_bounds__(256) void conv_bh_kernel(const float* __restrict__ W) {
    int gid = blockIdx.x * 256 + threadIdx.x;
    int n = gid >> 8;
    int kq = (gid & 255) << 2;
    float4 v = *(const float4*)(W + (size_t)n * KW + DD + kq);
    uint2 hq, lq;
    split4(v, hq, lq);
    int gate = n >> 10, j = n & 1023;
    int rp = (j >> 3) * 32 + gate * 8 + (j & 7);
    char* base = (char*)(g_bh + (size_t)rp * KHP2 + kq);
    *(uint2*)(base) = hq;
    *(uint2*)(base + 1024 * 2) = lq;
}

// ---------------- tcgen05 x-GEMM: Gx = A'[32768xKP] . B'[4096xKP]^T + bias --------
#define OF_A 1024
#define OF_B 33792
#define GEMM_SMEM (33792 + 2 * 32768)
__global__ __launch_bounds__(256, 2) void gemm_tc(const float* __restrict__ bias) {
#if HAS_TC5
    extern __shared__ __align__(1024) char smem[];
    uint32_t sbase = smem_u32(smem);
    int tid = threadIdx.x;
    int wid = tid >> 5, lane = tid & 31;
    int bn = blockIdx.x;  // 0..15
    int bm = blockIdx.y;  // 0..255

    if (wid == 0) {
        asm volatile("tcgen05.alloc.cta_group::1.sync.aligned.shared::cta.b32 [%0], %1;"
                     :: "r"(sbase), "r"(256) : "memory");
        asm volatile("tcgen05.relinquish_alloc_permit.cta_group::1.sync.aligned;");
    }
    if (tid == 0) {
        mbar_init(sbase + 8, 1);
        mbar_init(sbase + 16, 1);
    }
    __syncthreads();
    uint32_t tmem;
    asm volatile("ld.shared.b32 %0, [%1];" : "=r"(tmem) : "r"(sbase));

    const __nv_bfloat16* Ab = g_a + (size_t)(bm * 128) * KP;
    const __nv_bfloat16* Bb = g_b + (size_t)(bn * 256) * KP;

    uint4 ra[4], rb[8];

#define LOAD_STAGE(k0)                                                                  \
    do {                                                                                \
        _Pragma("unroll") for (int i = 0; i < 4; i++) {                                 \
            int ch = tid + i * 256;                                                     \
            ra[i] = *(const uint4*)(Ab + (size_t)(ch >> 3) * KP + (k0) + (ch & 7) * 8); \
        }                                                                               \
        _Pragma("unroll") for (int i = 0; i < 8; i++) {                                 \
            int ch = tid + i * 256;                                                     \
            rb[i] = *(const uint4*)(Bb + (size_t)(ch >> 3) * KP + (k0) + (ch & 7) * 8); \
        }                                                                               \
    } while (0)

#define STORE_STAGE(buf)                                                     \
    do {                                                                     \
        _Pragma("unroll") for (int i = 0; i < 4; i++) {                      \
            int ch = tid + i * 256;                                          \
            uint32_t off = (uint32_t)(ch >> 3) * 128 + (ch & 7) * 16;        \
            *(uint4*)(smem + OF_A + (buf) * 16384 + SWZ(off)) = ra[i];       \
        }                                                                    \
        _Pragma("unroll") for (int i = 0; i < 8; i++) {                      \
            int ch = tid + i * 256;                                          \
            uint32_t off = (uint32_t)(ch >> 3) * 128 + (ch & 7) * 16;        \
            *(uint4*)(smem + OF_B + (buf) * 32768 + SWZ(off)) = rb[i];       \
        }                                                                    \
    } while (0)

    LOAD_STAGE(0);
    for (int s = 0; s < 48; s++) {
        int buf = s & 1;
        if (s >= 2) mbar_wait(sbase + 8 + buf * 8, ((s >> 1) & 1) ^ 1);
        STORE_STAGE(buf);
        __syncthreads();
        if (wid == 0) {
            asm volatile("fence.proxy.async.shared::cta;" ::: "memory");
            if (elect1()) {
                uint64_t ad = MK_DESC(sbase + OF_A + buf * 16384);
                uint64_t bd = MK_DESC(sbase + OF_B + buf * 32768);
#pragma unroll
                for (int k = 0; k < 4; k++)
                    mma_f16_ss(tmem, ad + k * 2, bd + k * 2, GEMM_IDESC,
                               (s > 0 || k > 0) ? 1u : 0u);
                tc_commit(sbase + 8 + buf * 8);
            }
        }
        if (s + 1 < 48) LOAD_STAGE((s + 1) * 64);
    }
    mbar_wait(sbase + 8, 1);
    mbar_wait(sbase + 16, 1);
    asm volatile("tcgen05.fence::after_thread_sync;" ::: "memory");

    if (wid < 4) {
        int m = bm * 128 + wid * 32 + lane;
        int s_ = m & 511, b_ = m >> 9;
        float* orow = g_gx + (size_t)(s_ * BB + b_) * G4H + bn * 256;
        const float* brow = bias + bn * 256;
#pragma unroll 1
        for (int cb = 0; cb < 256; cb += 32) {
            uint32_t r[32];
            LDTM_X32(r, tmem + cb);
            asm volatile("tcgen05.wait::ld.sync.aligned;" ::: "memory");
#pragma unroll
            for (int j = 0; j < 32; j += 4) {
                float4 v;
                v.x = __uint_as_float(r[j + 0]) + __ldg(brow + cb + j + 0);
                v.y = __uint_as_float(r[j + 1]) + __ldg(brow + cb + j + 1);
                v.z = __uint_as_float(r[j + 2]) + __ldg(brow + cb + j + 2);
                v.w = __uint_as_float(r[j + 3]) + __ldg(brow + cb + j + 3);
                *(float4*)(orow + cb + j) = v;
            }
        }
    }
    __syncthreads();
    if (wid == 0) {
        asm volatile("tcgen05.dealloc.cta_group::1.sync.aligned.b32 %0, %1;"
                     :: "r"(tmem), "r"(256));
    }
#else
    // SIMT fallback for the non-arch-specific PTX pass (never selected on GB300).
    int tid = threadIdx.x;
    int bn = blockIdx.x, bm = blockIdx.y;
    for (int idx = tid; idx < 128 * 256; idx += 256) {
        int mi = idx >> 8, ni = idx & 255;
        int m = bm * 128 + mi, n = bn * 256 + ni;
        const __nv_bfloat16* ar = g_a + (size_t)m * KP;
        const __nv_bfloat16* br = g_b + (size_t)n * KP;
        float acc = 0.f;
        for (int k = 0; k < KP; k += 2) {
            __nv_bfloat162 av = *(const __nv_bfloat162*)(ar + k);
            __nv_bfloat162 bv = *(const __nv_bfloat162*)(br + k);
            acc += __bfloat162float(av.x) * __bfloat162float(bv.x);
            acc += __bfloat162float(av.y) * __bfloat162float(bv.y);
        }
        int s_ = m & 511, b_ = m >> 9;
        g_gx[(size_t)(s_ * BB + b_) * G4H + n] = acc + bias[n];
    }
#endif
}

// ---------------- grid barrier ----------------
__device__ __forceinline__ void grid_bar() {
    __syncthreads();
    if (threadIdx.x == 0) {
        __threadfence();
        unsigned e = g_epoch;
        unsigned old = atomicAdd(&g_arrive, 1);
        if (old == RNBLK - 1) {
            g_arrive = 0;
            __threadfence();
            atomicExch(&g_epoch, e + 1);
        } else {
            while (*(volatile unsigned*)&g_epoch == e) {}
            __threadfence();
        }
    }
    __syncthreads();
}

// ---------------- persistent tcgen05 recurrent kernel ----------------
// 128 CTAs, each owns 8 h-cols (32 gate cols). Wh' [Whi|Wlo] (32x2048 bf16 = 128KB)
// resident in SMEM; h' [hi|lo] broadcast from L2 per step; c in registers (warps 0-1).
// MMA: M=128 (h rows duplicated to lanes 64-127), N=32 — validated test_mma config.
#define RW_OFF 1024
#define RA_OFF (RW_OFF + 131072)   // 132096
#define RGX_OFF (RA_OFF + 32768)   // 164864
#define RSMEM (RGX_OFF + 8192)     // 173056
__global__ __launch_bounds__(RNTHR, 1) void lstm_tc(float* __restrict__ outp) {
#if HAS_TC5
    extern __shared__ __align__(1024) char smem[];
    uint32_t sbase = smem_u32(smem);
    int tid = threadIdx.x, wid = tid >> 5, lane = tid & 31;
    int cta = blockIdx.x;
    int jb = cta * 8;

    if (wid == 0) {
        asm volatile("tcgen05.alloc.cta_group::1.sync.aligned.shared::cta.b32 [%0], %1;"
                     :: "r"(sbase), "r"(32) : "memory");
        asm volatile("tcgen05.relinquish_alloc_permit.cta_group::1.sync.aligned;");
    }
    if (tid == 0) {
        mbar_init(sbase + 8, 1);
        mbar_init(sbase + 16, 1);
    }
    __syncthreads();
    uint32_t tmem;
    asm volatile("ld.shared.b32 %0, [%1];" : "=r"(tmem) : "r"(sbase));

    // Load resident Wh' slice: 32 chunks x (32 rows x 128B), SW128 swizzled.
    {
        const __nv_bfloat16* wsrc = g_bh + (size_t)cta * 32 * KHP2;
        for (int i = tid; i < 8192; i += RNTHR) {  // 8192 uint4 = 128KB
            int lc = i >> 8, q = i & 255;          // row 0..31, 16B-unit 0..255
            uint4 v = *(const uint4*)(wsrc + (size_t)lc * KHP2 + q * 8);
            int c = q >> 3;
            uint32_t off = (uint32_t)lc * 128 + (q & 7) * 16;
            *(uint4*)(smem + RW_OFF + c * 4096 + SWZ(off)) = v;
        }
    }
    __syncthreads();

    float* gxs = (float*)(smem + RGX_OFF);
    uint32_t ph0 = 0, ph1 = 0;
    float creg[8];
#pragma unroll
    for (int u = 0; u < 8; u++) creg[u] = 0.f;
    int m_ep = wid * 32 + lane;  // epilogue row (wid<2)

    int ar = tid >> 2, akq = tid & 3;  // A staging: row 0..63, 32B-quarter

    for (int t = 0; t < SS; t++) {
        const __nv_bfloat16* __restrict__ hin = g_hsp[t & 1];
        __nv_bfloat16* __restrict__ hout = g_hsp[(t + 1) & 1];
        const float* __restrict__ gxt = g_gx + (size_t)t * BB * G4H;

        // stage Gx tile [64][32] into smem, coalesced
        {
            int b = tid >> 2, gate = tid & 3;
            const float* src = gxt + (size_t)b * G4H + gate * HH + jb;
            float4 v0 = *(const float4*)src;
            float4 v1 = *(const float4*)(src + 4);
            float* dst = gxs + b * 32 + gate * 8;
            *(float4*)dst = v0;
            *(float4*)(dst + 4) = v1;
        }

        // prefetch chunk 0 (source chunk 0 = hi)
        uint4 a0 = *(const uint4*)(hin + (size_t)ar * KHP2 + akq * 16);
        uint4 a1 = *(const uint4*)(hin + (size_t)ar * KHP2 + akq * 16 + 8);

        // 48 stages: s<16: hi*Whi, 16..31: hi*Wlo, 32..47: lo*Whi
        for (int s = 0; s < 48; s++) {
            int buf = s & 1;
            uint32_t n = buf ? ph1 : ph0;
            if (n >= 1) mbar_wait(sbase + 8 + buf * 8, (n - 1) & 1);
            {
                uint32_t off = (uint32_t)ar * 128 + akq * 32;
                char* abase = smem + RA_OFF + buf * 16384;
                uint32_t so0 = SWZ(off), so1 = SWZ(off + 16);
                *(uint4*)(abase + so0) = a0;
                *(uint4*)(abase + so1) = a1;
                // duplicate rows into lanes 64..127 (off+8192; swizzle-period safe)
                *(uint4*)(abase + so0 + 8192) = a0;
                *(uint4*)(abase + so1 + 8192) = a1;
            }
            // prefetch next chunk while MMA runs
            if (s + 1 < 48) {
                int sn = s + 1;
                int ks = (sn < 16) ? sn : sn - 16;  // 16..31->hi again, 32..47->lo (16..31)
                const __nv_bfloat16* asrc = hin + (size_t)ar * KHP2 + ks * 64 + akq * 16;
                a0 = *(const uint4*)asrc;
                a1 = *(const uint4*)(asrc + 8);
            }
            __syncthreads();
            if (wid == 0) {
                asm volatile("fence.proxy.async.shared::cta;" ::: "memory");
                if (elect1()) {
                    int kb = (s < 32) ? s : s - 32;  // B chunk: Whi 0..15, Wlo 16..31
                    uint64_t ad = MK_DESC(sbase + RA_OFF + buf * 16384);
                    uint64_t bd = MK_DESC(sbase + RW_OFF + kb * 4096);
#pragma unroll
                    for (int k = 0; k < 4; k++)
                        mma_f16_ss(tmem, ad + k * 2, bd + k * 2, REC_IDESC,
                                   (s > 0 || k > 0) ? 1u : 0u);
                    tc_commit(sbase + 8 + buf * 8);
                }
            }
            if (buf) ph1++; else ph0++;
        }

        // epilogue
        mbar_wait(sbase + 8, (ph0 - 1) & 1);
        mbar_wait(sbase + 16, (ph1 - 1) & 1);
        asm volatile("tcgen05.fence::after_thread_sync;" ::: "memory");
        if (wid < 2) {
            uint32_t rr[32];
            LDTM_X32(rr, tmem);
            asm volatile("tcgen05.wait::ld.sync.aligned;" ::: "memory");
            int m = m_ep;
            float hv[8];
#pragma unroll
            for (int u = 0; u < 8; u++) {
                float gi = __uint_as_float(rr[u]) + gxs[m * 32 + u];
                float gf = __uint_as_float(rr[8 + u]) + gxs[m * 32 + 8 + u];
                float go = __uint_as_float(rr[16 + u]) + gxs[m * 32 + 16 + u];
                float gg = __uint_as_float(rr[24 + u]) + gxs[m * 32 + 24 + u];
                float si = 1.f / (1.f + __expf(-gi));
                float sf = 1.f / (1.f + __expf(-gf));
                float so = 1.f / (1.f + __expf(-go));
                float cn = sf * creg[u] + si * tanhf(gg);
                creg[u] = cn;
                hv[u] = so * tanhf(cn);
            }
            // outputs[b][t][j]
            float* op = outp + ((size_t)m * SS + t) * HH + jb;
            float4 o0 = {hv[0], hv[1], hv[2], hv[3]};
            float4 o1 = {hv[4], hv[5], hv[6], hv[7]};
            *(float4*)op = o0;
            *(float4*)(op + 4) = o1;
            // h packed write: [hi | lo]
            uint32_t hp[4], lp[4];
#pragma unroll
            for (int q = 0; q < 4; q++) {
                __nv_bfloat16 b0 = __float2bfloat16(hv[2 * q]);
                __nv_bfloat16 b1 = __float2bfloat16(hv[2 * q + 1]);
                __nv_bfloat16 c0 = __float2bfloat16(hv[2 * q] - __bfloat162float(b0));
                __nv_bfloat16 c1 = __float2bfloat16(hv[2 * q + 1] - __bfloat162float(b1));
                hp[q] = (uint32_t)__bfloat16_as_ushort(b0) |
                        ((uint32_t)__bfloat16_as_ushort(b1) << 16);
                lp[q] = (uint32_t)__bfloat16_as_ushort(c0) |
                        ((uint32_t)__bfloat16_as_ushort(c1) << 16);
            }
            char* hbase = (char*)(hout + (size_t)m * KHP2 + jb);
            *(uint4*)hbase = *(uint4*)hp;
            *(uint4*)(hbase + 2048) = *(uint4*)lp;
            if (t == SS - 1) {
#pragma unroll
                for (int u = 0; u < 8; u++) {
                    g_hfin[(size_t)m * HH + jb + u] = hv[u];
                    g_cfin[(size_t)m * HH + jb + u] = creg[u];
                }
            }
        }
        grid_bar();
    }
    __syncthreads();
    if (wid == 0) {
        asm volatile("tcgen05.dealloc.cta_group::1.sync.aligned.b32 %0, %1;"
                     :: "r"(tmem), "r"(32));
    }
#else
    // SIMT fallback (never selected at runtime on GB300; correctness-preserving).
    int tid = threadIdx.x;
    int cta = blockIdx.x;
    int jb = cta * 8;
    __shared__ float cs[512];
    __shared__ float hb2[512];
    for (int i = tid; i < 512; i += RNTHR) cs[i] = 0.f;
    __syncthreads();
    for (int t = 0; t < SS; t++) {
        const __nv_bfloat16* hin = g_hsp[t & 1];
        __nv_bfloat16* hout = g_hsp[(t + 1) & 1];
        const float* gxt = g_gx + (size_t)t * BB * G4H;
        for (int e = tid; e < 512; e += RNTHR) {
            int m = e >> 3, u = e & 7;
            float g4[4];
            for (int gate = 0; gate < 4; gate++) {
                const __nv_bfloat16* arow = hin + (size_t)m * KHP2;
                const __nv_bfloat16* brow = g_bh + (size_t)(cta * 32 + gate * 8 + u) * KHP2;
                float acc = 0.f;
                for (int k = 0; k < 1024; k++) {
                    float ah = __bfloat162float(arow[k]);
                    float al = __bfloat162float(arow[1024 + k]);
                    float wh = __bfloat162float(brow[k]);
                    float wl = __bfloat162float(brow[1024 + k]);
                    acc += ah * wh + ah * wl + al * wh;
                }
                g4[gate] = acc + gxt[(size_t)m * G4H + gate * HH + jb + u];
            }
            float si = 1.f / (1.f + __expf(-g4[0]));
            float sf = 1.f / (1.f + __expf(-g4[1]));
            float so = 1.f / (1.f + __expf(-g4[2]));
            float cn = sf * cs[e] + si * tanhf(g4[3]);
            cs[e] = cn;
            float h = so * tanhf(cn);
            hb2[e] = h;
            outp[((size_t)m * SS + t) * HH + jb + u] = h;
            if (t == SS - 1) {
                g_hfin[(size_t)m * HH + jb + u] = h;
                g_cfin[(size_t)m * HH + jb + u] = cn;
            }
        }
        grid_bar();
        for (int e = tid; e < 512; e += RNTHR) {
            int m = e >> 3, u = e & 7;
            float h = hb2[e];
            __nv_bfloat16 hb = __float2bfloat16(h);
            __nv_bfloat16 lb = __float2bfloat16(h - __bfloat162float(hb));
            hout[(size_t)m * KHP2 + jb + u] = hb;
            hout[(size_t)m * KHP2 + 1024 + jb + u] = lb;
        }
        grid_bar();
    }
#endif
}

// ---------------- tail: final (h, c) leaves if present ----------------
__global__ void tail_kernel(float* __restrict__ dst, int nh, int nc) {
    int i = blockIdx.x * blockDim.x + threadIdx.x;
    if (i < nh) dst[OUT_MAIN + i] = g_hfin[i];
    if (i < nc) dst[OUT_MAIN + 65536 + i] = g_cfin[i];
}

// ---------------- launch ----------------
extern "C" void kernel_launch(void* const* d_in, const int* in_sizes, int n_in,
                              void* d_out, int out_size) {
    const float* x = nullptr;
    const float* W = nullptr;
    const float* bias = nullptr;
    for (int i = 0; i < n_in; i++) {
        if (in_sizes[i] == BB * SS * DD) x = (const float*)d_in[i];
        else if (in_sizes[i] == G4H * KW) W = (const float*)d_in[i];
        else if (in_sizes[i] == G4H) bias = (const float*)d_in[i];
    }
    float* out = (float*)d_out;

    cudaFuncSetAttribute(gemm_tc, cudaFuncAttributeMaxDynamicSharedMemorySize, GEMM_SMEM);
    cudaFuncSetAttribute(lstm_tc, cudaFuncAttributeMaxDynamicSharedMemorySize, RSMEM);

    init_kernel<<<(BB * KHP2 / 2 + 1023) / 1024, 1024>>>();
    conv_a_kernel<<<(BB * SS * 256) / 256, 256>>>(x);
    conv_b_kernel<<<(G4H * 256) / 256, 256>>>(W);
    conv_bh_kernel<<<(G4H * 256) / 256, 256>>>(W);

    gemm_tc<<<dim3(16, 256), 256, GEMM_SMEM>>>(bias);

    lstm_tc<<<RNBLK, RNTHR, RSMEM>>>(out);

    if (out_size > OUT_MAIN) {
        int extra = out_size - OUT_MAIN;
        int nh = extra < 65536 ? extra : 65536;
        int nc = extra > 65536 ? (extra - 65536 < 65536 ? extra - 65536 : 65536) : 0;
        tail_kernel<<<64, 1024>>>(out, nh, nc);
    }
}

// round 7
// speedup vs baseline: 3.5361x; 1.5326x over previous
#include <cuda_runtime.h>
#include <cuda_bf16.h>
#include <math.h>
#include <stdint.h>

// Problem constants
#define BB 64
#define SS 512
#define DD 1024
#define HH 1024
#define G4H 4096          // 4*H
#define KW 2048           // D+H
#define KP 3072           // split-bf16 packed K for x-GEMM (hi|hi|lo)
#define KHP2 2048         // packed h cols: [hi | lo]
#define OUT_MAIN 33554432 // B*S*H
#define RNBLK 128
#define RNTHR 256

// tcgen05 availability: only in the arch-specific (sm_103a/sm_100a) compile pass.
#if defined(__CUDA_ARCH_FEAT_SM103_ALL) || defined(__CUDA_ARCH_FEAT_SM100_ALL) || \
    (defined(__CUDA_ARCH_SPECIFIC__) && (__CUDA_ARCH_SPECIFIC__ >= 1000))
#define HAS_TC5 1
#else
#define HAS_TC5 0
#endif

// ---------------- device scratch (no allocs allowed) ----------------
__device__ float g_gx[(size_t)SS * BB * G4H];            // [s][b][4H]
__device__ __nv_bfloat16 g_a[(size_t)(BB * SS) * KP];    // A' split-bf16 [32768][3072]
__device__ __nv_bfloat16 g_b[(size_t)G4H * KP];          // B' split-bf16 [4096][3072]
__device__ __nv_bfloat16 g_bh[(size_t)RNBLK * 32 * KHP2];// Wh' [128*32][2048] = [Whi|Wlo]
__device__ __nv_bfloat16 g_hsp[2][(size_t)BB * KHP2];    // h' [b][2048] = [hi|lo], dbl buf
__device__ float g_hfin[BB * HH];
__device__ float g_cfin[BB * HH];
__device__ unsigned g_arrive;
__device__ unsigned g_epoch;

// ---------------- PTX helpers ----------------
__device__ __forceinline__ uint32_t smem_u32(const void* p) {
    uint32_t a;
    asm("{ .reg .u64 t; cvta.to.shared.u64 t, %1; cvt.u32.u64 %0, t; }" : "=r"(a) : "l"(p));
    return a;
}

#if HAS_TC5
__device__ __forceinline__ uint32_t elect1() {
    uint32_t p;
    asm volatile("{\n\t.reg .pred p;\n\telect.sync _|p, 0xFFFFFFFF;\n\tselp.b32 %0, 1, 0, p;\n\t}" : "=r"(p));
    return p;
}
__device__ __forceinline__ void mbar_init(uint32_t mbar, uint32_t cnt) {
    asm volatile("mbarrier.init.shared.b64 [%0], %1;" :: "r"(mbar), "r"(cnt) : "memory");
}
__device__ __forceinline__ void mbar_wait(uint32_t mbar, uint32_t parity) {
    asm volatile(
        "{\n\t.reg .pred P1;\n\t"
        "WL%=:\n\t"
        "mbarrier.try_wait.parity.acquire.cta.shared::cta.b64 P1, [%0], %1, 0x989680;\n\t"
        "@P1 bra.uni WD%=;\n\t"
        "bra.uni WL%=;\n\t"
        "WD%=:\n\t}"
        :: "r"(mbar), "r"(parity) : "memory");
}
__device__ __forceinline__ void mma_f16_ss(uint32_t d, uint64_t ad, uint64_t bd,
                                           uint32_t idesc, uint32_t en) {
    asm volatile(
        "{\n\t.reg .pred p;\n\tsetp.ne.u32 p, %5, 0;\n\t"
        "tcgen05.mma.cta_group::1.kind::f16 [%0], %1, %2, %3, {%4, %4, %4, %4}, p;\n\t}"
        :: "r"(d), "l"(ad), "l"(bd), "r"(idesc), "r"(0u), "r"(en) : "memory");
}
__device__ __forceinline__ void tc_commit(uint32_t mbar) {
    asm volatile("tcgen05.commit.cta_group::1.mbarrier::arrive::one.shared::cluster.b64 [%0];"
                 :: "r"(mbar) : "memory");
}
#define LDTM_X32(r, addr) \
    asm volatile( \
        "tcgen05.ld.sync.aligned.32x32b.x32.b32 " \
        "{%0, %1, %2, %3, %4, %5, %6, %7, %8, %9, %10, %11, %12, %13, %14, %15, " \
        " %16, %17, %18, %19, %20, %21, %22, %23, %24, %25, %26, %27, %28, %29, %30, %31}, [%32];" \
        : "=r"((r)[0]), "=r"((r)[1]), "=r"((r)[2]), "=r"((r)[3]), \
          "=r"((r)[4]), "=r"((r)[5]), "=r"((r)[6]), "=r"((r)[7]), \
          "=r"((r)[8]), "=r"((r)[9]), "=r"((r)[10]), "=r"((r)[11]), \
          "=r"((r)[12]), "=r"((r)[13]), "=r"((r)[14]), "=r"((r)[15]), \
          "=r"((r)[16]), "=r"((r)[17]), "=r"((r)[18]), "=r"((r)[19]), \
          "=r"((r)[20]), "=r"((r)[21]), "=r"((r)[22]), "=r"((r)[23]), \
          "=r"((r)[24]), "=r"((r)[25]), "=r"((r)[26]), "=r"((r)[27]), \
          "=r"((r)[28]), "=r"((r)[29]), "=r"((r)[30]), "=r"((r)[31]) \
        : "r"(addr))
#endif  // HAS_TC5

static constexpr uint64_t DESC_BASE_SW128 =
    (2ULL << 61) | (1ULL << 46) | (64ULL << 32) | (1ULL << 16);
#define MK_DESC(a) (DESC_BASE_SW128 | (((uint64_t)((a) >> 4)) & 0x3FFF))
#define SWZ(o) ((o) ^ (((o) >> 3) & 0x70))

// idesc: kind::f16, dtype=F32, a/b=BF16
#define GEMM_IDESC ((1u << 4) | (1u << 7) | (1u << 10) | ((256u / 8u) << 17) | ((128u / 16u) << 24))
// M=128, N=32 — identical to the validated test_mma.cu config (0x8080490)
#define REC_IDESC  ((1u << 4) | (1u << 7) | (1u << 10) | ((32u / 8u) << 17) | ((128u / 16u) << 24))

// ---------------- init: zero h0 packed buffer 0 ----------------
__global__ void init_kernel() {
    int i = blockIdx.x * blockDim.x + threadIdx.x;
    if (i < (BB * KHP2) / 2) ((uint32_t*)g_hsp[0])[i] = 0u;
}

// ---------------- split-bf16 conversion ----------------
__device__ __forceinline__ void split4(float4 v, uint2& hq, uint2& lq) {
    __nv_bfloat16 h0 = __float2bfloat16(v.x), h1 = __float2bfloat16(v.y);
    __nv_bfloat16 h2 = __float2bfloat16(v.z), h3 = __float2bfloat16(v.w);
    __nv_bfloat16 l0 = __float2bfloat16(v.x - __bfloat162float(h0));
    __nv_bfloat16 l1 = __float2bfloat16(v.y - __bfloat162float(h1));
    __nv_bfloat16 l2 = __float2bfloat16(v.z - __bfloat162float(h2));
    __nv_bfloat16 l3 = __float2bfloat16(v.w - __bfloat162float(h3));
    hq.x = (uint32_t)__bfloat16_as_ushort(h0) | ((uint32_t)__bfloat16_as_ushort(h1) << 16);
    hq.y = (uint32_t)__bfloat16_as_ushort(h2) | ((uint32_t)__bfloat16_as_ushort(h3) << 16);
    lq.x = (uint32_t)__bfloat16_as_ushort(l0) | ((uint32_t)__bfloat16_as_ushort(l1) << 16);
    lq.y = (uint32_t)__bfloat16_as_ushort(l2) | ((uint32_t)__bfloat16_as_ushort(l3) << 16);
}

// A' = [hi | hi | lo] from x [32768][1024]
__global__ __launch_bounds__(256) void conv_a_kernel(const float* __restrict__ x) {
    int gid = blockIdx.x * 256 + threadIdx.x;
    int m = gid >> 8;
    int kq = (gid & 255) << 2;
    float4 v = *(const float4*)(x + (size_t)m * DD + kq);
    uint2 hq, lq;
    split4(v, hq, lq);
    char* base = (char*)(g_a + (size_t)m * KP + kq);
    *(uint2*)(base) = hq;
    *(uint2*)(base + 1024 * 2) = hq;
    *(uint2*)(base + 2048 * 2) = lq;
}

// B' = [hi | lo | hi] from W rows [4096][2048], x-part cols 0..1023
__global__ __launch_bounds__(256) void conv_b_kernel(const float* __restrict__ W) {
    int gid = blockIdx.x * 256 + threadIdx.x;
    int n = gid >> 8;
    int kq = (gid & 255) << 2;
    float4 v = *(const float4*)(W + (size_t)n * KW + kq);
    uint2 hq, lq;
    split4(v, hq, lq);
    char* base = (char*)(g_b + (size_t)n * KP + kq);
    *(uint2*)(base) = hq;
    *(uint2*)(base + 1024 * 2) = lq;
    *(uint2*)(base + 2048 * 2) = hq;
}

// Wh' packed per recurrent CTA: row rp = cta*32 + gate*8 + u, [Whi | Wlo] (2048),
// source W rows n = gate*1024 + cta*8 + u, h-part cols 1024..2047.
__global__ __launch_bounds__(256) void conv_bh_kernel(const float* __restrict__ W) {
    int gid = blockIdx.x * 256 + threadIdx.x;
    int n = gid >> 8;
    int kq = (gid & 255) << 2;
    float4 v = *(const float4*)(W + (size_t)n * KW + DD + kq);
    uint2 hq, lq;
    split4(v, hq, lq);
    int gate = n >> 10, j = n & 1023;
    int rp = (j >> 3) * 32 + gate * 8 + (j & 7);
    char* base = (char*)(g_bh + (size_t)rp * KHP2 + kq);
    *(uint2*)(base) = hq;
    *(uint2*)(base + 1024 * 2) = lq;
}

// ---------------- tcgen05 x-GEMM: Gx = A'[32768xKP] . B'[4096xKP]^T + bias --------
#define OF_A 1024
#define OF_B 33792
#define GEMM_SMEM (33792 + 2 * 32768)
__global__ __launch_bounds__(256, 2) void gemm_tc(const float* __restrict__ bias) {
#if HAS_TC5
    extern __shared__ __align__(1024) char smem[];
    uint32_t sbase = smem_u32(smem);
    int tid = threadIdx.x;
    int wid = tid >> 5, lane = tid & 31;
    int bn = blockIdx.x;  // 0..15
    int bm = blockIdx.y;  // 0..255

    if (wid == 0) {
        asm volatile("tcgen05.alloc.cta_group::1.sync.aligned.shared::cta.b32 [%0], %1;"
                     :: "r"(sbase), "r"(256) : "memory");
        asm volatile("tcgen05.relinquish_alloc_permit.cta_group::1.sync.aligned;");
    }
    if (tid == 0) {
        mbar_init(sbase + 8, 1);
        mbar_init(sbase + 16, 1);
    }
    __syncthreads();
    uint32_t tmem;
    asm volatile("ld.shared.b32 %0, [%1];" : "=r"(tmem) : "r"(sbase));

    const __nv_bfloat16* Ab = g_a + (size_t)(bm * 128) * KP;
    const __nv_bfloat16* Bb = g_b + (size_t)(bn * 256) * KP;

    uint4 ra[4], rb[8];

#define LOAD_STAGE(k0)                                                                  \
    do {                                                                                \
        _Pragma("unroll") for (int i = 0; i < 4; i++) {                                 \
            int ch = tid + i * 256;                                                     \
            ra[i] = *(const uint4*)(Ab + (size_t)(ch >> 3) * KP + (k0) + (ch & 7) * 8); \
        }                                                                               \
        _Pragma("unroll") for (int i = 0; i < 8; i++) {                                 \
            int ch = tid + i * 256;                                                     \
            rb[i] = *(const uint4*)(Bb + (size_t)(ch >> 3) * KP + (k0) + (ch & 7) * 8); \
        }                                                                               \
    } while (0)

#define STORE_STAGE(buf)                                                     \
    do {                                                                     \
        _Pragma("unroll") for (int i = 0; i < 4; i++) {                      \
            int ch = tid + i * 256;                                          \
            uint32_t off = (uint32_t)(ch >> 3) * 128 + (ch & 7) * 16;        \
            *(uint4*)(smem + OF_A + (buf) * 16384 + SWZ(off)) = ra[i];       \
        }                                                                    \
        _Pragma("unroll") for (int i = 0; i < 8; i++) {                      \
            int ch = tid + i * 256;                                          \
            uint32_t off = (uint32_t)(ch >> 3) * 128 + (ch & 7) * 16;        \
            *(uint4*)(smem + OF_B + (buf) * 32768 + SWZ(off)) = rb[i];       \
        }                                                                    \
    } while (0)

    LOAD_STAGE(0);
    for (int s = 0; s < 48; s++) {
        int buf = s & 1;
        if (s >= 2) mbar_wait(sbase + 8 + buf * 8, ((s >> 1) & 1) ^ 1);
        STORE_STAGE(buf);
        __syncthreads();
        if (wid == 0) {
            asm volatile("fence.proxy.async.shared::cta;" ::: "memory");
            if (elect1()) {
                uint64_t ad = MK_DESC(sbase + OF_A + buf * 16384);
                uint64_t bd = MK_DESC(sbase + OF_B + buf * 32768);
#pragma unroll
                for (int k = 0; k < 4; k++)
                    mma_f16_ss(tmem, ad + k * 2, bd + k * 2, GEMM_IDESC,
                               (s > 0 || k > 0) ? 1u : 0u);
                tc_commit(sbase + 8 + buf * 8);
            }
        }
        if (s + 1 < 48) LOAD_STAGE((s + 1) * 64);
    }
    mbar_wait(sbase + 8, 1);
    mbar_wait(sbase + 16, 1);
    asm volatile("tcgen05.fence::after_thread_sync;" ::: "memory");

    if (wid < 4) {
        int m = bm * 128 + wid * 32 + lane;
        int s_ = m & 511, b_ = m >> 9;
        float* orow = g_gx + (size_t)(s_ * BB + b_) * G4H + bn * 256;
        const float* brow = bias + bn * 256;
#pragma unroll 1
        for (int cb = 0; cb < 256; cb += 32) {
            uint32_t r[32];
            LDTM_X32(r, tmem + cb);
            asm volatile("tcgen05.wait::ld.sync.aligned;" ::: "memory");
#pragma unroll
            for (int j = 0; j < 32; j += 4) {
                float4 v;
                v.x = __uint_as_float(r[j + 0]) + __ldg(brow + cb + j + 0);
                v.y = __uint_as_float(r[j + 1]) + __ldg(brow + cb + j + 1);
                v.z = __uint_as_float(r[j + 2]) + __ldg(brow + cb + j + 2);
                v.w = __uint_as_float(r[j + 3]) + __ldg(brow + cb + j + 3);
                *(float4*)(orow + cb + j) = v;
            }
        }
    }
    __syncthreads();
    if (wid == 0) {
        asm volatile("tcgen05.dealloc.cta_group::1.sync.aligned.b32 %0, %1;"
                     :: "r"(tmem), "r"(256));
    }
#else
    // SIMT fallback for the non-arch-specific PTX pass (never selected on GB300).
    int tid = threadIdx.x;
    int bn = blockIdx.x, bm = blockIdx.y;
    for (int idx = tid; idx < 128 * 256; idx += 256) {
        int mi = idx >> 8, ni = idx & 255;
        int m = bm * 128 + mi, n = bn * 256 + ni;
        const __nv_bfloat16* ar = g_a + (size_t)m * KP;
        const __nv_bfloat16* br = g_b + (size_t)n * KP;
        float acc = 0.f;
        for (int k = 0; k < KP; k += 2) {
            __nv_bfloat162 av = *(const __nv_bfloat162*)(ar + k);
            __nv_bfloat162 bv = *(const __nv_bfloat162*)(br + k);
            acc += __bfloat162float(av.x) * __bfloat162float(bv.x);
            acc += __bfloat162float(av.y) * __bfloat162float(bv.y);
        }
        int s_ = m & 511, b_ = m >> 9;
        g_gx[(size_t)(s_ * BB + b_) * G4H + n] = acc + bias[n];
    }
#endif
}

// ---------------- grid barrier ----------------
__device__ __forceinline__ void grid_bar() {
    __syncthreads();
    if (threadIdx.x == 0) {
        __threadfence();
        unsigned e = g_epoch;
        unsigned old = atomicAdd(&g_arrive, 1);
        if (old == RNBLK - 1) {
            g_arrive = 0;
            __threadfence();
            atomicExch(&g_epoch, e + 1);
        } else {
            while (*(volatile unsigned*)&g_epoch == e) {}
            __threadfence();
        }
    }
    __syncthreads();
}

// ---------------- persistent tcgen05 recurrent kernel ----------------
// 128 CTAs, each owns 8 h-cols (32 gate cols). Wh' [Whi|Wlo] (32x2048 bf16 = 128KB)
// resident in SMEM. A tile M=128: rows 0-63 = h_hi, rows 64-127 = h_lo. 16 stages
// of one 16KB A chunk, each issuing 8 MMAs (Whi-chunk + Wlo-chunk, one commit).
// Epilogue combines D[m] + D[m+64] = (hi+lo)(Whi+Wlo) — full 4-term product.
#define RW_OFF 1024
#define RA_OFF (RW_OFF + 131072)    // 132096
#define RGX_OFF (RA_OFF + 32768)    // 164864
#define RLO_OFF (RGX_OFF + 8192)    // 173056
#define RSMEM (RLO_OFF + 8448)      // 181504
__global__ __launch_bounds__(RNTHR, 1) void lstm_tc(float* __restrict__ outp) {
#if HAS_TC5
    extern __shared__ __align__(1024) char smem[];
    uint32_t sbase = smem_u32(smem);
    int tid = threadIdx.x, wid = tid >> 5, lane = tid & 31;
    int cta = blockIdx.x;
    int jb = cta * 8;

    if (wid == 0) {
        asm volatile("tcgen05.alloc.cta_group::1.sync.aligned.shared::cta.b32 [%0], %1;"
                     :: "r"(sbase), "r"(32) : "memory");
        asm volatile("tcgen05.relinquish_alloc_permit.cta_group::1.sync.aligned;");
    }
    if (tid == 0) {
        mbar_init(sbase + 8, 1);
        mbar_init(sbase + 16, 1);
    }
    __syncthreads();
    uint32_t tmem;
    asm volatile("ld.shared.b32 %0, [%1];" : "=r"(tmem) : "r"(sbase));

    // Load resident Wh' slice: 32 chunks x (32 rows x 128B), SW128 swizzled.
    {
        const __nv_bfloat16* wsrc = g_bh + (size_t)cta * 32 * KHP2;
        for (int i = tid; i < 8192; i += RNTHR) {  // 8192 uint4 = 128KB
            int lc = i >> 8, q = i & 255;          // row 0..31, 16B-unit 0..255
            uint4 v = *(const uint4*)(wsrc + (size_t)lc * KHP2 + q * 8);
            int c = q >> 3;
            uint32_t off = (uint32_t)lc * 128 + (q & 7) * 16;
            *(uint4*)(smem + RW_OFF + c * 4096 + SWZ(off)) = v;
        }
    }
    __syncthreads();

    float* gxs = (float*)(smem + RGX_OFF);
    float* loD = (float*)(smem + RLO_OFF);
    uint32_t ph0 = 0, ph1 = 0;
    float creg[8];
#pragma unroll
    for (int u = 0; u < 8; u++) creg[u] = 0.f;
    int m_ep = wid * 32 + lane;  // epilogue row (wid<2)

    // A staging ids: row 0..127 (hi rows 0-63, lo rows 64-127), 64B half
    int ar = tid >> 1, ah = tid & 1;
    size_t rowoff = (ar < 64 ? (size_t)ar * KHP2 : (size_t)(ar - 64) * KHP2 + 1024) + ah * 32;
    uint32_t soff[4];
#pragma unroll
    for (int i = 0; i < 4; i++) soff[i] = SWZ((uint32_t)ar * 128 + ah * 64 + i * 16);

    for (int t = 0; t < SS; t++) {
        const __nv_bfloat16* __restrict__ hin = g_hsp[t & 1];
        __nv_bfloat16* __restrict__ hout = g_hsp[(t + 1) & 1];
        const float* __restrict__ gxt = g_gx + (size_t)t * BB * G4H;

        // stage Gx tile [64][32] into smem, coalesced
        {
            int b = tid >> 2, gate = tid & 3;
            const float* src = gxt + (size_t)b * G4H + gate * HH + jb;
            float4 v0 = *(const float4*)src;
            float4 v1 = *(const float4*)(src + 4);
            float* dst = gxs + b * 32 + gate * 8;
            *(float4*)dst = v0;
            *(float4*)(dst + 4) = v1;
        }

        // prefetch chunk 0
        uint4 pf[4];
#pragma unroll
        for (int i = 0; i < 4; i++)
            pf[i] = *(const uint4*)(hin + rowoff + i * 8);

        // 16 stages; stage s: A chunk s (K=64), MMAs vs Whi chunk s and Wlo chunk s+16
        for (int s = 0; s < 16; s++) {
            int buf = s & 1;
            uint32_t n = buf ? ph1 : ph0;
            if (n >= 1) mbar_wait(sbase + 8 + buf * 8, (n - 1) & 1);
            {
                char* abase = smem + RA_OFF + buf * 16384;
#pragma unroll
                for (int i = 0; i < 4; i++)
                    *(uint4*)(abase + soff[i]) = pf[i];
            }
            if (s + 1 < 16) {
#pragma unroll
                for (int i = 0; i < 4; i++)
                    pf[i] = *(const uint4*)(hin + rowoff + (s + 1) * 64 + i * 8);
            }
            __syncthreads();
            if (wid == 0) {
                asm volatile("fence.proxy.async.shared::cta;" ::: "memory");
                if (elect1()) {
                    uint64_t ad = MK_DESC(sbase + RA_OFF + buf * 16384);
                    uint64_t bd0 = MK_DESC(sbase + RW_OFF + s * 4096);
                    uint64_t bd1 = MK_DESC(sbase + RW_OFF + (s + 16) * 4096);
#pragma unroll
                    for (int k = 0; k < 4; k++)
                        mma_f16_ss(tmem, ad + k * 2, bd0 + k * 2, REC_IDESC,
                                   (s > 0 || k > 0) ? 1u : 0u);
#pragma unroll
                    for (int k = 0; k < 4; k++)
                        mma_f16_ss(tmem, ad + k * 2, bd1 + k * 2, REC_IDESC, 1u);
                    tc_commit(sbase + 8 + buf * 8);
                }
            }
            if (buf) ph1++; else ph0++;
        }

        // epilogue: D rows 0-63 = hi-part, rows 64-127 = lo-part; combine.
        mbar_wait(sbase + 8, (ph0 - 1) & 1);
        mbar_wait(sbase + 16, (ph1 - 1) & 1);
        asm volatile("tcgen05.fence::after_thread_sync;" ::: "memory");
        uint32_t rr[32];
        if (wid < 4) {
            LDTM_X32(rr, tmem);
            asm volatile("tcgen05.wait::ld.sync.aligned;" ::: "memory");
        }
        if (wid >= 2 && wid < 4) {
            int m = (wid - 2) * 32 + lane;
            float* lr = loD + m * 33;
#pragma unroll
            for (int j = 0; j < 32; j++) lr[j] = __uint_as_float(rr[j]);
        }
        __syncthreads();
        if (wid < 2) {
            int m = m_ep;
            const float* lr = loD + m * 33;
            float hv[8];
#pragma unroll
            for (int u = 0; u < 8; u++) {
                float gi = __uint_as_float(rr[u]) + lr[u] + gxs[m * 32 + u];
                float gf = __uint_as_float(rr[8 + u]) + lr[8 + u] + gxs[m * 32 + 8 + u];
                float go = __uint_as_float(rr[16 + u]) + lr[16 + u] + gxs[m * 32 + 16 + u];
                float gg = __uint_as_float(rr[24 + u]) + lr[24 + u] + gxs[m * 32 + 24 + u];
                float si = 1.f / (1.f + __expf(-gi));
                float sf = 1.f / (1.f + __expf(-gf));
                float so = 1.f / (1.f + __expf(-go));
                float cn = sf * creg[u] + si * tanhf(gg);
                creg[u] = cn;
                hv[u] = so * tanhf(cn);
            }
            // outputs[b][t][j]
            float* op = outp + ((size_t)m * SS + t) * HH + jb;
            float4 o0 = {hv[0], hv[1], hv[2], hv[3]};
            float4 o1 = {hv[4], hv[5], hv[6], hv[7]};
            *(float4*)op = o0;
            *(float4*)(op + 4) = o1;
            // h packed write: [hi | lo]
            uint32_t hp[4], lp[4];
#pragma unroll
            for (int q = 0; q < 4; q++) {
                __nv_bfloat16 b0 = __float2bfloat16(hv[2 * q]);
                __nv_bfloat16 b1 = __float2bfloat16(hv[2 * q + 1]);
                __nv_bfloat16 c0 = __float2bfloat16(hv[2 * q] - __bfloat162float(b0));
                __nv_bfloat16 c1 = __float2bfloat16(hv[2 * q + 1] - __bfloat162float(b1));
                hp[q] = (uint32_t)__bfloat16_as_ushort(b0) |
                        ((uint32_t)__bfloat16_as_ushort(b1) << 16);
                lp[q] = (uint32_t)__bfloat16_as_ushort(c0) |
                        ((uint32_t)__bfloat16_as_ushort(c1) << 16);
            }
            char* hbase = (char*)(hout + (size_t)m * KHP2 + jb);
            *(uint4*)hbase = *(uint4*)hp;
            *(uint4*)(hbase + 2048) = *(uint4*)lp;
            if (t == SS - 1) {
#pragma unroll
                for (int u = 0; u < 8; u++) {
                    g_hfin[(size_t)m * HH + jb + u] = hv[u];
                    g_cfin[(size_t)m * HH + jb + u] = creg[u];
                }
            }
        }
        grid_bar();
    }
    __syncthreads();
    if (wid == 0) {
        asm volatile("tcgen05.dealloc.cta_group::1.sync.aligned.b32 %0, %1;"
                     :: "r"(tmem), "r"(32));
    }
#else
    // SIMT fallback (never selected at runtime on GB300; correctness-preserving).
    int tid = threadIdx.x;
    int cta = blockIdx.x;
    int jb = cta * 8;
    __shared__ float cs[512];
    __shared__ float hb2[512];
    for (int i = tid; i < 512; i += RNTHR) cs[i] = 0.f;
    __syncthreads();
    for (int t = 0; t < SS; t++) {
        const __nv_bfloat16* hin = g_hsp[t & 1];
        __nv_bfloat16* hout = g_hsp[(t + 1) & 1];
        const float* gxt = g_gx + (size_t)t * BB * G4H;
        for (int e = tid; e < 512; e += RNTHR) {
            int m = e >> 3, u = e & 7;
            float g4[4];
            for (int gate = 0; gate < 4; gate++) {
                const __nv_bfloat16* arow = hin + (size_t)m * KHP2;
                const __nv_bfloat16* brow = g_bh + (size_t)(cta * 32 + gate * 8 + u) * KHP2;
                float acc = 0.f;
                for (int k = 0; k < 1024; k++) {
                    float ahv = __bfloat162float(arow[k]);
                    float alv = __bfloat162float(arow[1024 + k]);
                    float wh = __bfloat162float(brow[k]);
                    float wl = __bfloat162float(brow[1024 + k]);
                    acc += (ahv + alv) * (wh + wl);
                }
                g4[gate] = acc + gxt[(size_t)m * G4H + gate * HH + jb + u];
            }
            float si = 1.f / (1.f + __expf(-g4[0]));
            float sf = 1.f / (1.f + __expf(-g4[1]));
            float so = 1.f / (1.f + __expf(-g4[2]));
            float cn = sf * cs[e] + si * tanhf(g4[3]);
            cs[e] = cn;
            float h = so * tanhf(cn);
            hb2[e] = h;
            outp[((size_t)m * SS + t) * HH + jb + u] = h;
            if (t == SS - 1) {
                g_hfin[(size_t)m * HH + jb + u] = h;
                g_cfin[(size_t)m * HH + jb + u] = cn;
            }
        }
        grid_bar();
        for (int e = tid; e < 512; e += RNTHR) {
            int m = e >> 3, u = e & 7;
            float h = hb2[e];
            __nv_bfloat16 hb = __float2bfloat16(h);
            __nv_bfloat16 lb = __float2bfloat16(h - __bfloat162float(hb));
            hout[(size_t)m * KHP2 + jb + u] = hb;
            hout[(size_t)m * KHP2 + 1024 + jb + u] = lb;
        }
        grid_bar();
    }
#endif
}

// ---------------- tail: final (h, c) leaves if present ----------------
__global__ void tail_kernel(float* __restrict__ dst, int nh, int nc) {
    int i = blockIdx.x * blockDim.x + threadIdx.x;
    if (i < nh) dst[OUT_MAIN + i] = g_hfin[i];
    if (i < nc) dst[OUT_MAIN + 65536 + i] = g_cfin[i];
}

// ---------------- launch ----------------
extern "C" void kernel_launch(void* const* d_in, const int* in_sizes, int n_in,
                              void* d_out, int out_size) {
    const float* x = nullptr;
    const float* W = nullptr;
    const float* bias = nullptr;
    for (int i = 0; i < n_in; i++) {
        if (in_sizes[i] == BB * SS * DD) x = (const float*)d_in[i];
        else if (in_sizes[i] == G4H * KW) W = (const float*)d_in[i];
        else if (in_sizes[i] == G4H) bias = (const float*)d_in[i];
    }
    float* out = (float*)d_out;

    cudaFuncSetAttribute(gemm_tc, cudaFuncAttributeMaxDynamicSharedMemorySize, GEMM_SMEM);
    cudaFuncSetAttribute(lstm_tc, cudaFuncAttributeMaxDynamicSharedMemorySize, RSMEM);

    init_kernel<<<(BB * KHP2 / 2 + 1023) / 1024, 1024>>>();
    conv_a_kernel<<<(BB * SS * 256) / 256, 256>>>(x);
    conv_b_kernel<<<(G4H * 256) / 256, 256>>>(W);
    conv_bh_kernel<<<(G4H * 256) / 256, 256>>>(W);

    gemm_tc<<<dim3(16, 256), 256, GEMM_SMEM>>>(bias);

    lstm_tc<<<RNBLK, RNTHR, RSMEM>>>(out);

    if (out_size > OUT_MAIN) {
        int extra = out_size - OUT_MAIN;
        int nh = extra < 65536 ? extra : 65536;
        int nc = extra > 65536 ? (extra - 65536 < 65536 ? extra - 65536 : 65536) : 0;
        tail_kernel<<<64, 1024>>>(out, nh, nc);
    }
}

// round 8
// speedup vs baseline: 3.5728x; 1.0104x over previous
#include <cuda_runtime.h>
#include <cuda_bf16.h>
#include <math.h>
#include <stdint.h>

// Problem constants
#define BB 64
#define SS 512
#define DD 1024
#define HH 1024
#define G4H 4096          // 4*H
#define KW 2048           // D+H
#define KP 3072           // split-bf16 packed K for x-GEMM (hi|hi|lo)
#define KHP2 2048         // packed h cols: [hi | lo]
#define OUT_MAIN 33554432 // B*S*H
#define RNBLK 128
#define RNTHR 256

// tcgen05 availability: only in the arch-specific (sm_103a/sm_100a) compile pass.
#if defined(__CUDA_ARCH_FEAT_SM103_ALL) || defined(__CUDA_ARCH_FEAT_SM100_ALL) || \
    (defined(__CUDA_ARCH_SPECIFIC__) && (__CUDA_ARCH_SPECIFIC__ >= 1000))
#define HAS_TC5 1
#else
#define HAS_TC5 0
#endif

// ---------------- device scratch (no allocs allowed) ----------------
// g_a tiled: [bm(256)][stage(48)][16384B: 128 rows x 64 bf16, SW128-swizzled]
// g_b tiled: [bn(16)][stage(48)][32768B: 256 rows x 64 bf16, SW128-swizzled]
__device__ float g_gx[(size_t)SS * BB * G4H];            // [s][b][4H]
__device__ __align__(1024) __nv_bfloat16 g_a[(size_t)(BB * SS) * KP];
__device__ __align__(1024) __nv_bfloat16 g_b[(size_t)G4H * KP];
__device__ __nv_bfloat16 g_bh[(size_t)RNBLK * 32 * KHP2];// Wh' [128*32][2048] = [Whi|Wlo]
__device__ __nv_bfloat16 g_hsp[2][(size_t)BB * KHP2];    // h' [b][2048] = [hi|lo], dbl buf
__device__ float g_hfin[BB * HH];
__device__ float g_cfin[BB * HH];
__device__ unsigned g_arrive;
__device__ unsigned g_epoch;

// ---------------- PTX helpers ----------------
__device__ __forceinline__ uint32_t smem_u32(const void* p) {
    uint32_t a;
    asm("{ .reg .u64 t; cvta.to.shared.u64 t, %1; cvt.u32.u64 %0, t; }" : "=r"(a) : "l"(p));
    return a;
}

#if HAS_TC5
__device__ __forceinline__ uint32_t elect1() {
    uint32_t p;
    asm volatile("{\n\t.reg .pred p;\n\telect.sync _|p, 0xFFFFFFFF;\n\tselp.b32 %0, 1, 0, p;\n\t}" : "=r"(p));
    return p;
}
__device__ __forceinline__ void mbar_init(uint32_t mbar, uint32_t cnt) {
    asm volatile("mbarrier.init.shared.b64 [%0], %1;" :: "r"(mbar), "r"(cnt) : "memory");
}
__device__ __forceinline__ void mbar_expect_tx(uint32_t mbar, uint32_t bytes) {
    asm volatile("mbarrier.arrive.expect_tx.shared.b64 _, [%0], %1;"
                 :: "r"(mbar), "r"(bytes) : "memory");
}
__device__ __forceinline__ void bulk_g2s(uint32_t dst, const void* src, uint32_t bytes,
                                         uint32_t mbar) {
    asm volatile(
        "cp.async.bulk.shared::cta.global.mbarrier::complete_tx::bytes [%0], [%1], %2, [%3];"
        :: "r"(dst), "l"(src), "r"(bytes), "r"(mbar) : "memory");
}
__device__ __forceinline__ void mbar_wait(uint32_t mbar, uint32_t parity) {
    asm volatile(
        "{\n\t.reg .pred P1;\n\t"
        "WL%=:\n\t"
        "mbarrier.try_wait.parity.acquire.cta.shared::cta.b64 P1, [%0], %1, 0x989680;\n\t"
        "@P1 bra.uni WD%=;\n\t"
        "bra.uni WL%=;\n\t"
        "WD%=:\n\t}"
        :: "r"(mbar), "r"(parity) : "memory");
}
__device__ __forceinline__ void mma_f16_ss(uint32_t d, uint64_t ad, uint64_t bd,
                                           uint32_t idesc, uint32_t en) {
    asm volatile(
        "{\n\t.reg .pred p;\n\tsetp.ne.u32 p, %5, 0;\n\t"
        "tcgen05.mma.cta_group::1.kind::f16 [%0], %1, %2, %3, {%4, %4, %4, %4}, p;\n\t}"
        :: "r"(d), "l"(ad), "l"(bd), "r"(idesc), "r"(0u), "r"(en) : "memory");
}
__device__ __forceinline__ void tc_commit(uint32_t mbar) {
    asm volatile("tcgen05.commit.cta_group::1.mbarrier::arrive::one.shared::cluster.b64 [%0];"
                 :: "r"(mbar) : "memory");
}
#define LDTM_X32(r, addr) \
    asm volatile( \
        "tcgen05.ld.sync.aligned.32x32b.x32.b32 " \
        "{%0, %1, %2, %3, %4, %5, %6, %7, %8, %9, %10, %11, %12, %13, %14, %15, " \
        " %16, %17, %18, %19, %20, %21, %22, %23, %24, %25, %26, %27, %28, %29, %30, %31}, [%32];" \
        : "=r"((r)[0]), "=r"((r)[1]), "=r"((r)[2]), "=r"((r)[3]), \
          "=r"((r)[4]), "=r"((r)[5]), "=r"((r)[6]), "=r"((r)[7]), \
          "=r"((r)[8]), "=r"((r)[9]), "=r"((r)[10]), "=r"((r)[11]), \
          "=r"((r)[12]), "=r"((r)[13]), "=r"((r)[14]), "=r"((r)[15]), \
          "=r"((r)[16]), "=r"((r)[17]), "=r"((r)[18]), "=r"((r)[19]), \
          "=r"((r)[20]), "=r"((r)[21]), "=r"((r)[22]), "=r"((r)[23]), \
          "=r"((r)[24]), "=r"((r)[25]), "=r"((r)[26]), "=r"((r)[27]), \
          "=r"((r)[28]), "=r"((r)[29]), "=r"((r)[30]), "=r"((r)[31]) \
        : "r"(addr))
#endif  // HAS_TC5

static constexpr uint64_t DESC_BASE_SW128 =
    (2ULL << 61) | (1ULL << 46) | (64ULL << 32) | (1ULL << 16);
#define MK_DESC(a) (DESC_BASE_SW128 | (((uint64_t)((a) >> 4)) & 0x3FFF))
#define SWZ(o) ((o) ^ (((o) >> 3) & 0x70))

// idesc: kind::f16, dtype=F32, a/b=BF16
#define GEMM_IDESC ((1u << 4) | (1u << 7) | (1u << 10) | ((256u / 8u) << 17) | ((128u / 16u) << 24))
// M=128, N=32 — identical to the validated test_mma.cu config (0x8080490)
#define REC_IDESC  ((1u << 4) | (1u << 7) | (1u << 10) | ((32u / 8u) << 17) | ((128u / 16u) << 24))

// ---------------- init: zero h0 packed buffer 0 ----------------
__global__ void init_kernel() {
    int i = blockIdx.x * blockDim.x + threadIdx.x;
    if (i < (BB * KHP2) / 2) ((uint32_t*)g_hsp[0])[i] = 0u;
}

// ---------------- split-bf16 conversion ----------------
__device__ __forceinline__ void split4(float4 v, uint2& hq, uint2& lq) {
    __nv_bfloat16 h0 = __float2bfloat16(v.x), h1 = __float2bfloat16(v.y);
    __nv_bfloat16 h2 = __float2bfloat16(v.z), h3 = __float2bfloat16(v.w);
    __nv_bfloat16 l0 = __float2bfloat16(v.x - __bfloat162float(h0));
    __nv_bfloat16 l1 = __float2bfloat16(v.y - __bfloat162float(h1));
    __nv_bfloat16 l2 = __float2bfloat16(v.z - __bfloat162float(h2));
    __nv_bfloat16 l3 = __float2bfloat16(v.w - __bfloat162float(h3));
    hq.x = (uint32_t)__bfloat16_as_ushort(h0) | ((uint32_t)__bfloat16_as_ushort(h1) << 16);
    hq.y = (uint32_t)__bfloat16_as_ushort(h2) | ((uint32_t)__bfloat16_as_ushort(h3) << 16);
    lq.x = (uint32_t)__bfloat16_as_ushort(l0) | ((uint32_t)__bfloat16_as_ushort(l1) << 16);
    lq.y = (uint32_t)__bfloat16_as_ushort(l2) | ((uint32_t)__bfloat16_as_ushort(l3) << 16);
}

// tiled destination byte offset inside g_a: tile row r (0..127), packed col kp
__device__ __forceinline__ size_t a_off(int bm, int r, int kp) {
    int s = kp >> 6, c = kp & 63;
    return ((size_t)(bm * 48 + s) << 14) + SWZ((uint32_t)(r * 128 + c * 2));
}
// tiled destination byte offset inside g_b: tile row r (0..255), packed col kp
__device__ __forceinline__ size_t b_off(int bn, int r, int kp) {
    int s = kp >> 6, c = kp & 63;
    return ((size_t)(bn * 48 + s) << 15) + SWZ((uint32_t)(r * 128 + c * 2));
}

// A' = [hi | hi | lo] from x [32768][1024] -> tiled swizzled g_a
__global__ __launch_bounds__(256) void conv_a_kernel(const float* __restrict__ x) {
    int gid = blockIdx.x * 256 + threadIdx.x;
    int m = gid >> 8;
    int kq = (gid & 255) << 2;
    float4 v = *(const float4*)(x + (size_t)m * DD + kq);
    uint2 hq, lq;
    split4(v, hq, lq);
    int bm = m >> 7, r = m & 127;
    char* base = (char*)g_a;
    *(uint2*)(base + a_off(bm, r, kq)) = hq;
    *(uint2*)(base + a_off(bm, r, 1024 + kq)) = hq;
    *(uint2*)(base + a_off(bm, r, 2048 + kq)) = lq;
}

// B' = [hi | lo | hi] from W rows [4096][2048] (x-part cols) -> tiled swizzled g_b
__global__ __launch_bounds__(256) void conv_b_kernel(const float* __restrict__ W) {
    int gid = blockIdx.x * 256 + threadIdx.x;
    int n = gid >> 8;
    int kq = (gid & 255) << 2;
    float4 v = *(const float4*)(W + (size_t)n * KW + kq);
    uint2 hq, lq;
    split4(v, hq, lq);
    int bn = n >> 8, r = n & 255;
    char* base = (char*)g_b;
    *(uint2*)(base + b_off(bn, r, kq)) = hq;
    *(uint2*)(base + b_off(bn, r, 1024 + kq)) = lq;
    *(uint2*)(base + b_off(bn, r, 2048 + kq)) = hq;
}

// Wh' packed per recurrent CTA: row rp = cta*32 + gate*8 + u, [Whi | Wlo] (2048),
// source W rows n = gate*1024 + cta*8 + u, h-part cols 1024..2047.
__global__ __launch_bounds__(256) void conv_bh_kernel(const float* __restrict__ W) {
    int gid = blockIdx.x * 256 + threadIdx.x;
    int n = gid >> 8;
    int kq = (gid & 255) << 2;
    float4 v = *(const float4*)(W + (size_t)n * KW + DD + kq);
    uint2 hq, lq;
    split4(v, hq, lq);
    int gate = n >> 10, j = n & 1023;
    int rp = (j >> 3) * 32 + gate * 8 + (j & 7);
    char* base = (char*)(g_bh + (size_t)rp * KHP2 + kq);
    *(uint2*)(base) = hq;
    *(uint2*)(base + 1024 * 2) = lq;
}

// ---------------- tcgen05 x-GEMM: Gx = A'[32768xKP] . B'[4096xKP]^T + bias --------
// 1 CTA/SM, 128 threads, 4-deep cp.async.bulk pipeline, single control thread.
#define GSTG 49152
#define GEMM_SMEM (1024 + 4 * GSTG)  // 197632
__global__ __launch_bounds__(128, 1) void gemm_tc(const float* __restrict__ bias) {
#if HAS_TC5
    extern __shared__ __align__(1024) char smem[];
    uint32_t sbase = smem_u32(smem);
    int tid = threadIdx.x;
    int wid = tid >> 5, lane = tid & 31;
    int bn = blockIdx.x;  // 0..15
    int bm = blockIdx.y;  // 0..255

    if (wid == 0) {
        asm volatile("tcgen05.alloc.cta_group::1.sync.aligned.shared::cta.b32 [%0], %1;"
                     :: "r"(sbase), "r"(256) : "memory");
        asm volatile("tcgen05.relinquish_alloc_permit.cta_group::1.sync.aligned;");
    }
    // mbarriers: full[4] at +8..32, empty[4] at +40..64, done at +72
    if (tid == 0) {
#pragma unroll
        for (int i = 0; i < 4; i++) {
            mbar_init(sbase + 8 + i * 8, 1);
            mbar_init(sbase + 40 + i * 8, 1);
        }
        mbar_init(sbase + 72, 1);
    }
    __syncthreads();
    uint32_t tmem;
    asm volatile("ld.shared.b32 %0, [%1];" : "=r"(tmem) : "r"(sbase));

    const char* Asrc = (const char*)g_a + ((size_t)bm * 48 << 14);
    const char* Bsrc = (const char*)g_b + ((size_t)bn * 48 << 15);

    if (tid == 0) {
#pragma unroll
        for (int s = 0; s < 4; s++) {
            uint32_t full = sbase + 8 + s * 8;
            uint32_t dst = sbase + 1024 + s * GSTG;
            mbar_expect_tx(full, GSTG);
            bulk_g2s(dst, Asrc + (size_t)s * 16384, 16384, full);
            bulk_g2s(dst + 16384, Bsrc + (size_t)s * 32768, 32768, full);
        }
        for (int s = 0; s < 48; s++) {
            int b = s & 3;
            uint32_t p = (s >> 2) & 1;
            mbar_wait(sbase + 8 + b * 8, p);
            uint64_t ad = MK_DESC(sbase + 1024 + b * GSTG);
            uint64_t bd = MK_DESC(sbase + 1024 + b * GSTG + 16384);
#pragma unroll
            for (int k = 0; k < 4; k++)
                mma_f16_ss(tmem, ad + k * 2, bd + k * 2, GEMM_IDESC,
                           (s > 0 || k > 0) ? 1u : 0u);
            tc_commit(sbase + 40 + b * 8);
            if (s + 4 < 48) {
                mbar_wait(sbase + 40 + b * 8, p);  // MMA on buffer b done
                int sn = s + 4;
                uint32_t full = sbase + 8 + b * 8;
                uint32_t dst = sbase + 1024 + b * GSTG;
                mbar_expect_tx(full, GSTG);
                bulk_g2s(dst, Asrc + (size_t)sn * 16384, 16384, full);
                bulk_g2s(dst + 16384, Bsrc + (size_t)sn * 32768, 32768, full);
            }
        }
        tc_commit(sbase + 72);  // tracks all issued MMAs
    }
    mbar_wait(sbase + 72, 0);
    asm volatile("tcgen05.fence::after_thread_sync;" ::: "memory");

    {
        int m = bm * 128 + wid * 32 + lane;
        int s_ = m & 511, b_ = m >> 9;
        float* orow = g_gx + (size_t)(s_ * BB + b_) * G4H + bn * 256;
        const float* brow = bias + bn * 256;
#pragma unroll 1
        for (int cb = 0; cb < 256; cb += 32) {
            uint32_t r[32];
            LDTM_X32(r, tmem + cb);
            asm volatile("tcgen05.wait::ld.sync.aligned;" ::: "memory");
#pragma unroll
            for (int j = 0; j < 32; j += 4) {
                float4 v;
                v.x = __uint_as_float(r[j + 0]) + __ldg(brow + cb + j + 0);
                v.y = __uint_as_float(r[j + 1]) + __ldg(brow + cb + j + 1);
                v.z = __uint_as_float(r[j + 2]) + __ldg(brow + cb + j + 2);
                v.w = __uint_as_float(r[j + 3]) + __ldg(brow + cb + j + 3);
                *(float4*)(orow + cb + j) = v;
            }
        }
    }
    __syncthreads();
    if (wid == 0) {
        asm volatile("tcgen05.dealloc.cta_group::1.sync.aligned.b32 %0, %1;"
                     :: "r"(tmem), "r"(256));
    }
#else
    // SIMT fallback for the non-arch-specific PTX pass (never selected on GB300).
    int tid = threadIdx.x;
    int bn = blockIdx.x, bm = blockIdx.y;
    const char* ab = (const char*)g_a;
    const char* bb = (const char*)g_b;
    for (int idx = tid; idx < 128 * 256; idx += 128) {
        int mi = idx >> 8, ni = idx & 255;
        float acc = 0.f;
        for (int kp = 0; kp < KP; kp++) {
            __nv_bfloat16 av = *(const __nv_bfloat16*)(ab + a_off(bm, mi, kp));
            __nv_bfloat16 bv = *(const __nv_bfloat16*)(bb + b_off(bn, ni, kp));
            acc += __bfloat162float(av) * __bfloat162float(bv);
        }
        int m = bm * 128 + mi, n = bn * 256 + ni;
        int s_ = m & 511, b_ = m >> 9;
        g_gx[(size_t)(s_ * BB + b_) * G4H + n] = acc + bias[n];
    }
#endif
}

// ---------------- grid barrier ----------------
__device__ __forceinline__ void grid_bar() {
    __syncthreads();
    if (threadIdx.x == 0) {
        __threadfence();
        unsigned e = g_epoch;
        unsigned old = atomicAdd(&g_arrive, 1);
        if (old == RNBLK - 1) {
            g_arrive = 0;
            __threadfence();
            atomicExch(&g_epoch, e + 1);
        } else {
            while (*(volatile unsigned*)&g_epoch == e) {}
            __threadfence();
        }
    }
    __syncthreads();
}

// ---------------- persistent tcgen05 recurrent kernel (unchanged from R7) ---------
#define RW_OFF 1024
#define RA_OFF (RW_OFF + 131072)    // 132096
#define RGX_OFF (RA_OFF + 32768)    // 164864
#define RLO_OFF (RGX_OFF + 8192)    // 173056
#define RSMEM (RLO_OFF + 8448)      // 181504
__global__ __launch_bounds__(RNTHR, 1) void lstm_tc(float* __restrict__ outp) {
#if HAS_TC5
    extern __shared__ __align__(1024) char smem[];
    uint32_t sbase = smem_u32(smem);
    int tid = threadIdx.x, wid = tid >> 5, lane = tid & 31;
    int cta = blockIdx.x;
    int jb = cta * 8;

    if (wid == 0) {
        asm volatile("tcgen05.alloc.cta_group::1.sync.aligned.shared::cta.b32 [%0], %1;"
                     :: "r"(sbase), "r"(32) : "memory");
        asm volatile("tcgen05.relinquish_alloc_permit.cta_group::1.sync.aligned;");
    }
    if (tid == 0) {
        mbar_init(sbase + 8, 1);
        mbar_init(sbase + 16, 1);
    }
    __syncthreads();
    uint32_t tmem;
    asm volatile("ld.shared.b32 %0, [%1];" : "=r"(tmem) : "r"(sbase));

    // Load resident Wh' slice: 32 chunks x (32 rows x 128B), SW128 swizzled.
    {
        const __nv_bfloat16* wsrc = g_bh + (size_t)cta * 32 * KHP2;
        for (int i = tid; i < 8192; i += RNTHR) {
            int lc = i >> 8, q = i & 255;
            uint4 v = *(const uint4*)(wsrc + (size_t)lc * KHP2 + q * 8);
            int c = q >> 3;
            uint32_t off = (uint32_t)lc * 128 + (q & 7) * 16;
            *(uint4*)(smem + RW_OFF + c * 4096 + SWZ(off)) = v;
        }
    }
    __syncthreads();

    float* gxs = (float*)(smem + RGX_OFF);
    float* loD = (float*)(smem + RLO_OFF);
    uint32_t ph0 = 0, ph1 = 0;
    float creg[8];
#pragma unroll
    for (int u = 0; u < 8; u++) creg[u] = 0.f;
    int m_ep = wid * 32 + lane;

    int ar = tid >> 1, ah = tid & 1;
    size_t rowoff = (ar < 64 ? (size_t)ar * KHP2 : (size_t)(ar - 64) * KHP2 + 1024) + ah * 32;
    uint32_t soff[4];
#pragma unroll
    for (int i = 0; i < 4; i++) soff[i] = SWZ((uint32_t)ar * 128 + ah * 64 + i * 16);

    for (int t = 0; t < SS; t++) {
        const __nv_bfloat16* __restrict__ hin = g_hsp[t & 1];
        __nv_bfloat16* __restrict__ hout = g_hsp[(t + 1) & 1];
        const float* __restrict__ gxt = g_gx + (size_t)t * BB * G4H;

        {
            int b = tid >> 2, gate = tid & 3;
            const float* src = gxt + (size_t)b * G4H + gate * HH + jb;
            float4 v0 = *(const float4*)src;
            float4 v1 = *(const float4*)(src + 4);
            float* dst = gxs + b * 32 + gate * 8;
            *(float4*)dst = v0;
            *(float4*)(dst + 4) = v1;
        }

        uint4 pf[4];
#pragma unroll
        for (int i = 0; i < 4; i++)
            pf[i] = *(const uint4*)(hin + rowoff + i * 8);

        for (int s = 0; s < 16; s++) {
            int buf = s & 1;
            uint32_t n = buf ? ph1 : ph0;
            if (n >= 1) mbar_wait(sbase + 8 + buf * 8, (n - 1) & 1);
            {
                char* abase = smem + RA_OFF + buf * 16384;
#pragma unroll
                for (int i = 0; i < 4; i++)
                    *(uint4*)(abase + soff[i]) = pf[i];
            }
            if (s + 1 < 16) {
#pragma unroll
                for (int i = 0; i < 4; i++)
                    pf[i] = *(const uint4*)(hin + rowoff + (s + 1) * 64 + i * 8);
            }
            __syncthreads();
            if (wid == 0) {
                asm volatile("fence.proxy.async.shared::cta;" ::: "memory");
                if (elect1()) {
                    uint64_t ad = MK_DESC(sbase + RA_OFF + buf * 16384);
                    uint64_t bd0 = MK_DESC(sbase + RW_OFF + s * 4096);
                    uint64_t bd1 = MK_DESC(sbase + RW_OFF + (s + 16) * 4096);
#pragma unroll
                    for (int k = 0; k < 4; k++)
                        mma_f16_ss(tmem, ad + k * 2, bd0 + k * 2, REC_IDESC,
                                   (s > 0 || k > 0) ? 1u : 0u);
#pragma unroll
                    for (int k = 0; k < 4; k++)
                        mma_f16_ss(tmem, ad + k * 2, bd1 + k * 2, REC_IDESC, 1u);
                    tc_commit(sbase + 8 + buf * 8);
                }
            }
            if (buf) ph1++; else ph0++;
        }

        mbar_wait(sbase + 8, (ph0 - 1) & 1);
        mbar_wait(sbase + 16, (ph1 - 1) & 1);
        asm volatile("tcgen05.fence::after_thread_sync;" ::: "memory");
        uint32_t rr[32];
        if (wid < 4) {
            LDTM_X32(rr, tmem);
            asm volatile("tcgen05.wait::ld.sync.aligned;" ::: "memory");
        }
        if (wid >= 2 && wid < 4) {
            int m = (wid - 2) * 32 + lane;
            float* lr = loD + m * 33;
#pragma unroll
            for (int j = 0; j < 32; j++) lr[j] = __uint_as_float(rr[j]);
        }
        __syncthreads();
        if (wid < 2) {
            int m = m_ep;
            const float* lr = loD + m * 33;
            float hv[8];
#pragma unroll
            for (int u = 0; u < 8; u++) {
                float gi = __uint_as_float(rr[u]) + lr[u] + gxs[m * 32 + u];
                float gf = __uint_as_float(rr[8 + u]) + lr[8 + u] + gxs[m * 32 + 8 + u];
                float go = __uint_as_float(rr[16 + u]) + lr[16 + u] + gxs[m * 32 + 16 + u];
                float gg = __uint_as_float(rr[24 + u]) + lr[24 + u] + gxs[m * 32 + 24 + u];
                float si = 1.f / (1.f + __expf(-gi));
                float sf = 1.f / (1.f + __expf(-gf));
                float so = 1.f / (1.f + __expf(-go));
                float cn = sf * creg[u] + si * tanhf(gg);
                creg[u] = cn;
                hv[u] = so * tanhf(cn);
            }
            float* op = outp + ((size_t)m * SS + t) * HH + jb;
            float4 o0 = {hv[0], hv[1], hv[2], hv[3]};
            float4 o1 = {hv[4], hv[5], hv[6], hv[7]};
            *(float4*)op = o0;
            *(float4*)(op + 4) = o1;
            uint32_t hp[4], lp[4];
#pragma unroll
            for (int q = 0; q < 4; q++) {
                __nv_bfloat16 b0 = __float2bfloat16(hv[2 * q]);
                __nv_bfloat16 b1 = __float2bfloat16(hv[2 * q + 1]);
                __nv_bfloat16 c0 = __float2bfloat16(hv[2 * q] - __bfloat162float(b0));
                __nv_bfloat16 c1 = __float2bfloat16(hv[2 * q + 1] - __bfloat162float(b1));
                hp[q] = (uint32_t)__bfloat16_as_ushort(b0) |
                        ((uint32_t)__bfloat16_as_ushort(b1) << 16);
                lp[q] = (uint32_t)__bfloat16_as_ushort(c0) |
                        ((uint32_t)__bfloat16_as_ushort(c1) << 16);
            }
            char* hbase = (char*)(hout + (size_t)m * KHP2 + jb);
            *(uint4*)hbase = *(uint4*)hp;
            *(uint4*)(hbase + 2048) = *(uint4*)lp;
            if (t == SS - 1) {
#pragma unroll
                for (int u = 0; u < 8; u++) {
                    g_hfin[(size_t)m * HH + jb + u] = hv[u];
                    g_cfin[(size_t)m * HH + jb + u] = creg[u];
                }
            }
        }
        grid_bar();
    }
    __syncthreads();
    if (wid == 0) {
        asm volatile("tcgen05.dealloc.cta_group::1.sync.aligned.b32 %0, %1;"
                     :: "r"(tmem), "r"(32));
    }
#else
    // SIMT fallback (never selected at runtime on GB300; correctness-preserving).
    int tid = threadIdx.x;
    int cta = blockIdx.x;
    int jb = cta * 8;
    __shared__ float cs[512];
    __shared__ float hb2[512];
    for (int i = tid; i < 512; i += RNTHR) cs[i] = 0.f;
    __syncthreads();
    for (int t = 0; t < SS; t++) {
        const __nv_bfloat16* hin = g_hsp[t & 1];
        __nv_bfloat16* hout = g_hsp[(t + 1) & 1];
        const float* gxt = g_gx + (size_t)t * BB * G4H;
        for (int e = tid; e < 512; e += RNTHR) {
            int m = e >> 3, u = e & 7;
            float g4[4];
            for (int gate = 0; gate < 4; gate++) {
                const __nv_bfloat16* arow = hin + (size_t)m * KHP2;
                const __nv_bfloat16* brow = g_bh + (size_t)(cta * 32 + gate * 8 + u) * KHP2;
                float acc = 0.f;
                for (int k = 0; k < 1024; k++) {
                    float ahv = __bfloat162float(arow[k]);
                    float alv = __bfloat162float(arow[1024 + k]);
                    float wh = __bfloat162float(brow[k]);
                    float wl = __bfloat162float(brow[1024 + k]);
                    acc += (ahv + alv) * (wh + wl);
                }
                g4[gate] = acc + gxt[(size_t)m * G4H + gate * HH + jb + u];
            }
            float si = 1.f / (1.f + __expf(-g4[0]));
            float sf = 1.f / (1.f + __expf(-g4[1]));
            float so = 1.f / (1.f + __expf(-g4[2]));
            float cn = sf * cs[e] + si * tanhf(g4[3]);
            cs[e] = cn;
            float h = so * tanhf(cn);
            hb2[e] = h;
            outp[((size_t)m * SS + t) * HH + jb + u] = h;
            if (t == SS - 1) {
                g_hfin[(size_t)m * HH + jb + u] = h;
                g_cfin[(size_t)m * HH + jb + u] = cn;
            }
        }
        grid_bar();
        for (int e = tid; e < 512; e += RNTHR) {
            int m = e >> 3, u = e & 7;
            float h = hb2[e];
            __nv_bfloat16 hb = __float2bfloat16(h);
            __nv_bfloat16 lb = __float2bfloat16(h - __bfloat162float(hb));
            hout[(size_t)m * KHP2 + jb + u] = hb;
            hout[(size_t)m * KHP2 + 1024 + jb + u] = lb;
        }
        grid_bar();
    }
#endif
}

// ---------------- tail: final (h, c) leaves if present ----------------
__global__ void tail_kernel(float* __restrict__ dst, int nh, int nc) {
    int i = blockIdx.x * blockDim.x + threadIdx.x;
    if (i < nh) dst[OUT_MAIN + i] = g_hfin[i];
    if (i < nc) dst[OUT_MAIN + 65536 + i] = g_cfin[i];
}

// ---------------- launch ----------------
extern "C" void kernel_launch(void* const* d_in, const int* in_sizes, int n_in,
                              void* d_out, int out_size) {
    const float* x = nullptr;
    const float* W = nullptr;
    const float* bias = nullptr;
    for (int i = 0; i < n_in; i++) {
        if (in_sizes[i] == BB * SS * DD) x = (const float*)d_in[i];
        else if (in_sizes[i] == G4H * KW) W = (const float*)d_in[i];
        else if (in_sizes[i] == G4H) bias = (const float*)d_in[i];
    }
    float* out = (float*)d_out;

    cudaFuncSetAttribute(gemm_tc, cudaFuncAttributeMaxDynamicSharedMemorySize, GEMM_SMEM);
    cudaFuncSetAttribute(lstm_tc, cudaFuncAttributeMaxDynamicSharedMemorySize, RSMEM);

    init_kernel<<<(BB * KHP2 / 2 + 1023) / 1024, 1024>>>();
    conv_a_kernel<<<(BB * SS * 256) / 256, 256>>>(x);
    conv_b_kernel<<<(G4H * 256) / 256, 256>>>(W);
    conv_bh_kernel<<<(G4H * 256) / 256, 256>>>(W);

    gemm_tc<<<dim3(16, 256), 128, GEMM_SMEM>>>(bias);

    lstm_tc<<<RNBLK, RNTHR, RSMEM>>>(out);

    if (out_size > OUT_MAIN) {
        int extra = out_size - OUT_MAIN;
        int nh = extra < 65536 ? extra : 65536;
        int nc = extra > 65536 ? (extra - 65536 < 65536 ? extra - 65536 : 65536) : 0;
        tail_kernel<<<64, 1024>>>(out, nh, nc);
    }
}